// round 14
// baseline (speedup 1.0000x reference)
#include <cuda_runtime.h>
#include <cuda_fp16.h>
#include <math.h>

#define Bb 4
#define Ss 2048
#define Ee 1024
#define Hh 16
#define KVv 4
#define HDd 64
#define Rr 8
#define CDd 64
#define NQq 8
#define NCH 32
#define CHUNK 64
#define NTOK (Bb*Ss)      // 8192
#define NCAT 832          // aq 64 | kaq 64 | qb 128 | kb 32 | vb 32 | va 512

// ---------------- scratch (device globals; no cudaMalloc allowed) ----------------
// GEMM B operands stored TRANSPOSED [N][K] for cp.async. Single fp16 precision.
__device__ __align__(16) __half g_W[(size_t)NCAT * 1024];
__device__ __align__(16) __half g_oW[(size_t)1024 * 1024];
__device__ __align__(16) __half g_x[(size_t)NTOK * Ee];
__device__ __align__(16) __half g_a[(size_t)NTOK * Ee];
__device__ float g_cw[(size_t)1024 * 320];     // fp32 composite weights [k][n<320]
__device__ float g_bcat[NCAT];
__device__ float g_P[(size_t)NTOK * NCAT];
__device__ float g_v[(size_t)Bb * KVv * Ss * HDd];
__device__ float g_qf[(size_t)Bb * Hh * Ss * 16];
__device__ float g_kf[(size_t)Bb * KVv * Ss * 16];
__device__ float g_kvc[(size_t)Bb * KVv * NCH * 16 * 64];
__device__ float g_kfc[Bb * KVv * NCH * 16];

// ---------------- helpers ----------------
__device__ __forceinline__ void ld16(float* o, const float4* p) {
    float4 a = __ldg(p + 0), b = __ldg(p + 1), c = __ldg(p + 2), d = __ldg(p + 3);
    o[0] = a.x;  o[1] = a.y;  o[2] = a.z;  o[3] = a.w;
    o[4] = b.x;  o[5] = b.y;  o[6] = b.z;  o[7] = b.w;
    o[8] = c.x;  o[9] = c.y;  o[10] = c.z; o[11] = c.w;
    o[12] = d.x; o[13] = d.y; o[14] = d.z; o[15] = d.w;
}

#define MMA_F16(d, a, b0, b1)                                               \
    asm volatile("mma.sync.aligned.m16n8k16.row.col.f32.f16.f16.f32 "       \
                 "{%0,%1,%2,%3}, {%4,%5,%6,%7}, {%8,%9}, {%0,%1,%2,%3};"    \
                 : "+f"(d[0]), "+f"(d[1]), "+f"(d[2]), "+f"(d[3])           \
                 : "r"(a[0]), "r"(a[1]), "r"(a[2]), "r"(a[3]),              \
                   "r"(b0), "r"(b1))

#define LDM4A(rr, addr)                                                     \
    asm volatile("ldmatrix.sync.aligned.m8n8.x4.shared.b16 {%0,%1,%2,%3}, [%4];" \
                 : "=r"((rr)[0]), "=r"((rr)[1]), "=r"((rr)[2]), "=r"((rr)[3]) \
                 : "r"(addr))

// ---------------- K0a: composite weights, fp32, [k][n] (coalesced writes) ----------------
__global__ void pack_comp_kernel(
    const float* __restrict__ ctxW, const float* __restrict__ qaW, const float* __restrict__ kaW,
    const float* __restrict__ qbW,  const float* __restrict__ kbW, const float* __restrict__ vbW,
    const float* __restrict__ ctxb, const float* __restrict__ qab, const float* __restrict__ kab,
    const float* __restrict__ qbb,  const float* __restrict__ kbb, const float* __restrict__ vbb,
    const float* __restrict__ vab,  const float* __restrict__ qeW)
{
    const int k = blockIdx.x;
    const int tid = threadIdx.x;
    if (k < 1024) {
        __shared__ float sA[512], sKA[512], sCtx[64];
        for (int i = tid; i < 512; i += 256) { sA[i] = qaW[(size_t)k * 512 + i]; sKA[i] = kaW[(size_t)k * 512 + i]; }
        if (tid < 64) sCtx[tid] = ctxW[k * 64 + tid];
        __syncthreads();
        for (int n = tid; n < 320; n += 256) {
            float v = 0.f;
            if (n < 64) {
                int r = n >> 3, j = n & 7;
#pragma unroll 8
                for (int d = 0; d < 64; d++) v += sA[r * 64 + d] * __ldg(&qeW[d * 8 + j]);
            } else if (n < 128) {
                int m = n - 64, r = m >> 3, j = m & 7;
#pragma unroll 8
                for (int d = 0; d < 64; d++) v += sKA[r * 64 + d] * __ldg(&qeW[d * 8 + j]);
            } else if (n < 256) {
                int h = n - 128;
#pragma unroll 8
                for (int c = 0; c < 64; c++) v += sCtx[c] * __ldg(&qbW[c * 128 + h]);
            } else if (n < 288) {
                int h = n - 256;
#pragma unroll 8
                for (int c = 0; c < 64; c++) v += sCtx[c] * __ldg(&kbW[c * 32 + h]);
            } else {
                int h = n - 288;
#pragma unroll 8
                for (int c = 0; c < 64; c++) v += sCtx[c] * __ldg(&vbW[c * 32 + h]);
            }
            g_cw[(size_t)k * 320 + n] = v;
        }
    } else {
        for (int n = tid; n < NCAT; n += 256) {
            float v = 0.f;
            if (n < 64) {
                int r = n >> 3, j = n & 7;
                for (int d = 0; d < 64; d++) v += __ldg(&qab[r * 64 + d]) * __ldg(&qeW[d * 8 + j]);
            } else if (n < 128) {
                int m = n - 64, r = m >> 3, j = m & 7;
                for (int d = 0; d < 64; d++) v += __ldg(&kab[r * 64 + d]) * __ldg(&qeW[d * 8 + j]);
            } else if (n < 256) {
                int h = n - 128; v = qbb[h];
                for (int c = 0; c < 64; c++) v += ctxb[c] * __ldg(&qbW[c * 128 + h]);
            } else if (n < 288) {
                int h = n - 256; v = kbb[h];
                for (int c = 0; c < 64; c++) v += ctxb[c] * __ldg(&kbW[c * 32 + h]);
            } else if (n < 320) {
                int h = n - 288; v = vbb[h];
                for (int c = 0; c < 64; c++) v += ctxb[c] * __ldg(&vbW[c * 32 + h]);
            } else {
                v = vab[n - 320];
            }
            g_bcat[n] = v;
        }
    }
}

// ---------------- K0b: weights -> fp16, [n][k] layout ----------------
__global__ void pack_split_kernel(const float* __restrict__ vaW, const float* __restrict__ outW) {
    const size_t totalW = (size_t)NCAT * 1024;
    for (size_t i = blockIdx.x * blockDim.x + threadIdx.x; i < totalW; i += (size_t)gridDim.x * blockDim.x) {
        int k = (int)(i & 1023), n = (int)(i >> 10);
        float v = (n < 320) ? g_cw[(size_t)k * 320 + n]
                            : __ldg(&vaW[(size_t)k * 512 + (n - 320)]);
        g_W[i] = __float2half_rn(v);
    }
    const size_t total2 = (size_t)1024 * 1024;
    for (size_t i = blockIdx.x * blockDim.x + threadIdx.x; i < total2; i += (size_t)gridDim.x * blockDim.x) {
        int k = (int)(i & 1023);
        int n = (int)(i >> 10);
        g_oW[i] = __float2half_rn(__ldg(&outW[(size_t)k * 1024 + n]));
    }
}

// ---------------- K0c: x -> fp16 ----------------
__global__ void convx_kernel(const float* __restrict__ x) {
    const int total4 = NTOK * Ee / 4;
    for (int i = blockIdx.x * blockDim.x + threadIdx.x; i < total4; i += gridDim.x * blockDim.x) {
        float4 v = reinterpret_cast<const float4*>(x)[i];
        __half2 a; a.x = __float2half_rn(v.x); a.y = __float2half_rn(v.y);
        __half2 b; b.x = __float2half_rn(v.z); b.y = __float2half_rn(v.w);
        reinterpret_cast<__half2*>(g_x)[i * 2]     = a;
        reinterpret_cast<__half2*>(g_x)[i * 2 + 1] = b;
    }
}

// ---------------- tensor-core GEMM: fp16, high-reuse geometry ----------------
// C[M,N] = A[M,K] @ B^T, A/B fp16, B stored [N][K], fp32 accumulate.
// BM=256, BN=64, BK=64, 256 thr = 8 warps (4M x 2N), warp tile 64M x 32N.
// Per warp-ks: 4 A-ldm4 + 2 B-ldm4 -> 16 MMAs (0.375 ldm4/MMA).
// Stage: A 256x64 fp16 (32KB) @0 | B 64x64 (8KB) @32K; 40KB x 4 stages = 160KB, 1 CTA/SM.
// Rows 128B (8 x 16B chunks); swizzle: phys_chunk = ch ^ (row & 7).
// M, N, K all divide tiles exactly for both launches -> no guards.
#define STAGE_BYTES 40960u
#define NSTAGES 4

__global__ __launch_bounds__(256, 1)
void gemm_tc_kernel(int N, int K,
                    const __half* __restrict__ Ap, const __half* __restrict__ Bp,
                    const float* __restrict__ bias, const float* __restrict__ res,
                    float* __restrict__ C)
{
    extern __shared__ __align__(16) unsigned char dsm[];
    unsigned sbase = (unsigned)__cvta_generic_to_shared(dsm);
    const int bm = blockIdx.y * 256, bn = blockIdx.x * 64;
    const int tid = threadIdx.x, warp = tid >> 5, lane = tid & 31;
    const int wm = (warp >> 1) * 64, wn = (warp & 1) * 32;
    const int r = lane >> 2, cq = (lane & 3) * 2;

    // ---- persistent fill-task state: 10 chunks/thread (2560 total) ----
    const __half* gp[10];
    unsigned doff[10];
#pragma unroll
    for (int w = 0; w < 10; w++) {
        int tsk = tid + w * 256;             // 0..2559 16B-chunks of one stage
        int row, ch;
        unsigned abase;
        const __half* g;
        if (tsk < 2048) {                    // A: 256 rows x 8 chunks
            row = tsk >> 3; ch = tsk & 7;
            abase = 0u;
            g = Ap + (size_t)(bm + row) * K + ch * 8;
        } else {                             // B: 64 rows x 8 chunks
            int t2 = tsk - 2048;
            row = t2 >> 3; ch = t2 & 7;
            abase = 32768u;
            g = Bp + (size_t)(bn + row) * K + ch * 8;
        }
        gp[w] = g;
        doff[w] = abase + (unsigned)(row * 128 + ((ch ^ (row & 7)) << 4));
    }

#define FILL_STAGE(ST) do {                                                  \
    _Pragma("unroll")                                                        \
    for (int w = 0; w < 10; w++) {                                           \
        asm volatile("cp.async.cg.shared.global [%0], [%1], 16;"             \
                     :: "r"((ST) + doff[w]), "l"(gp[w]));                    \
        gp[w] += 64;                                                         \
    }                                                                        \
    asm volatile("cp.async.commit_group;");                                  \
} while (0)

    // ---- fragment base geometry ----
    const int rA = wm + (lane & 15);
    const int rB = wn + (lane & 15);
    const unsigned oAr = (unsigned)(rA * 128);
    const unsigned oBr = 32768u + (unsigned)(rB * 128);
    const unsigned swA = (unsigned)(rA & 7);
    const unsigned swB = (unsigned)(rB & 7);
    const unsigned c0 = (unsigned)(lane >> 4);

    float acc[4][4][4];
#pragma unroll
    for (int mt = 0; mt < 4; mt++)
#pragma unroll
        for (int j = 0; j < 4; j++)
#pragma unroll
            for (int q = 0; q < 4; q++) acc[mt][j][q] = 0.f;

    const int nk = K / 64;
    FILL_STAGE(sbase);
    FILL_STAGE(sbase + STAGE_BYTES);
    FILL_STAGE(sbase + 2u * STAGE_BYTES);

    for (int kt = 0; kt < nk; kt++) {
        asm volatile("cp.async.wait_group 2;");
        __syncthreads();
        if (kt + 3 < nk) {
            FILL_STAGE(sbase + (unsigned)((kt + 3) % NSTAGES) * STAGE_BYTES);
        } else {
            asm volatile("cp.async.commit_group;");
        }

        const unsigned st = sbase + (unsigned)(kt % NSTAGES) * STAGE_BYTES;
#pragma unroll
        for (int ks = 0; ks < 4; ks++) {
            const unsigned ch = (unsigned)(2 * ks) + c0;
            const unsigned aaddr = st + oAr + ((ch ^ swA) << 4);
            const unsigned baddr = st + oBr + ((ch ^ swB) << 4);
            unsigned ah[4][4];
            LDM4A(ah[0], aaddr);             // rows +16 keep swizzle (16 % 8 == 0)
            LDM4A(ah[1], aaddr + 2048u);
            LDM4A(ah[2], aaddr + 4096u);
            LDM4A(ah[3], aaddr + 6144u);
#pragma unroll
            for (int jj = 0; jj < 2; jj++) {
                unsigned bh[4];
                LDM4A(bh, baddr + (unsigned)jj * 2048u);
#pragma unroll
                for (int sub = 0; sub < 2; sub++)
#pragma unroll
                    for (int mt = 0; mt < 4; mt++)
                        MMA_F16(acc[mt][jj * 2 + sub], ah[mt], bh[sub], bh[2 + sub]);
            }
        }
    }

    // ---- epilogue: + bias (+ residual) ----
#pragma unroll
    for (int mt = 0; mt < 4; mt++) {
        int row0 = bm + wm + mt * 16 + r;
#pragma unroll
        for (int j = 0; j < 4; j++) {
            int col = bn + wn + j * 8 + cq;
            float b0v = bias[col], b1v = bias[col + 1];
            size_t o0 = (size_t)row0 * N + col;
            size_t o1 = (size_t)(row0 + 8) * N + col;
            float v0 = acc[mt][j][0] + b0v, v1 = acc[mt][j][1] + b1v;
            float v2 = acc[mt][j][2] + b0v, v3 = acc[mt][j][3] + b1v;
            if (res) {
                v0 += res[o0]; v1 += res[o0 + 1];
                v2 += res[o1]; v3 += res[o1 + 1];
            }
            C[o0] = v0; C[o0 + 1] = v1;
            C[o1] = v2; C[o1 + 1] = v3;
        }
    }
#undef FILL_STAGE
}

// ---------------- K2: v-assembly + quantum features ----------------
// g_P row layout: [aq 0:64 | kaq 64:128 | qb 128:256 | kb 256:288 | vb 288:320 | va 320:832]
__global__ __launch_bounds__(256, 6)
void tpa_feat_kernel(const float* __restrict__ qeb, const float* __restrict__ vqc,
                     const float* __restrict__ ent) {
    __shared__ float sP[NCAT];
    __shared__ float sVQ[48];
    __shared__ float sQEB[8];
    const int token = blockIdx.x;
    const int b = token / Ss, s = token % Ss;
    const int tid = threadIdx.x;

    const float4* p4 = reinterpret_cast<const float4*>(&g_P[(size_t)token * NCAT]);
    if (tid < NCAT / 4) reinterpret_cast<float4*>(sP)[tid] = p4[tid];
    if (tid >= 192 && tid < 240) sVQ[tid - 192] = __ldg(&vqc[tid - 192]);
    if (tid >= 240 && tid < 248) sQEB[tid - 240] = __ldg(&qeb[tid - 240]);
    __syncthreads();

    // v[kv,d] = sum_r va[r,d] * vb[r,kv]
    {
        int kv = tid >> 6, d = tid & 63;
        float av = 0.f;
#pragma unroll
        for (int r = 0; r < 8; r++) av += sP[320 + r * 64 + d] * sP[288 + r * 4 + kv];
        g_v[(((size_t)(b * KVv + kv)) * Ss + s) * 64 + d] = av;
    }

    // quantum features: one thread per (head, qubit), 20 heads x 8 = 160 threads
    const int oct = tid >> 3, j = tid & 7;
    if (oct < 20) {
        const float ev = __ldg(ent);
        float p = sQEB[j];
        if (oct < 16) {
#pragma unroll
            for (int r = 0; r < 8; r++) p += sP[128 + r * 16 + oct] * sP[r * 8 + j];
        } else {
#pragma unroll
            for (int r = 0; r < 8; r++) p += sP[256 + r * 4 + (oct - 16)] * sP[64 + r * 8 + j];
        }
        float f = tanhf(p) * 3.14159265358979323846f;
#pragma unroll
        for (int l = 0; l < 2; l++) {
            float a0 = sVQ[(l * 8 + j) * 3 + 0];
            float a1 = sVQ[(l * 8 + j) * 3 + 1];
            float a2 = sVQ[(l * 8 + j) * 3 + 2];
            float g = cosf(f + a0) * sinf(f + a1) + cosf(f + a2);
            int srcLane = ((tid & 31) & ~7) | ((j + 7) & 7);
            float gp = __shfl_sync(0xffffffffu, g, srcLane);
            f = g * (1.f + ev * gp);
        }
        float cv = cosf(f), sv = sinf(f);
        float nr = cv * cv + sv * sv;
        nr += __shfl_xor_sync(0xffffffffu, nr, 1);
        nr += __shfl_xor_sync(0xffffffffu, nr, 2);
        nr += __shfl_xor_sync(0xffffffffu, nr, 4);
        float inv = 1.f / (sqrtf(nr) + 1e-6f);
        float* dst = oct < 16
            ? &g_qf[(((size_t)(b * Hh + oct)) * Ss + s) * 16]
            : &g_kf[(((size_t)(b * KVv + (oct - 16))) * Ss + s) * 16];
        dst[j]     = cv * inv;
        dst[j + 8] = sv * inv;
    }
}

// ---------------- Pass A: per-chunk sums of kf (x) v and kf ----------------
__global__ __launch_bounds__(64, 8)
void passA_kernel() {
    const int blk = blockIdx.x;            // (b*KV+kv)*NCH + c
    const int c = blk % NCH;
    const int bk = blk / NCH;
    const int tid = threadIdx.x;           // d
    const float4* kfb = reinterpret_cast<const float4*>(&g_kf[(((size_t)bk) * Ss + c * CHUNK) * 16]);
    const float* vb = &g_v[(((size_t)bk) * Ss + c * CHUNK) * 64];
    float acc[16];
#pragma unroll
    for (int f = 0; f < 16; f++) acc[f] = 0.f;
    float kfs = 0.f;
    for (int t = 0; t < CHUNK; t++) {
        float vd = vb[t * 64 + tid];
        float kv[16]; ld16(kv, kfb + t * 4);
#pragma unroll
        for (int f = 0; f < 16; f++) acc[f] += kv[f] * vd;
        if (tid < 16) kfs += __ldg(&g_kf[(((size_t)bk) * Ss + c * CHUNK + t) * 16 + tid]);
    }
#pragma unroll
    for (int f = 0; f < 16; f++) g_kvc[((size_t)blk * 16 + f) * 64 + tid] = acc[f];
    if (tid < 16) g_kfc[blk * 16 + tid] = kfs;
}

// ---------------- Pass C: chunk prefix + within-chunk scan + query eval ----------------
__global__ __launch_bounds__(64, 8)
void passC_kernel() {
    const int blk = blockIdx.x;
    const int c = blk % NCH;
    const int bk = blk / NCH;
    const int b = bk / KVv, kvh = bk % KVv;
    const int tid = threadIdx.x;           // d
    float st[16], kc[16];
#pragma unroll
    for (int f = 0; f < 16; f++) { st[f] = 0.f; kc[f] = 0.f; }
    for (int cp = 0; cp < c; cp++) {
        int blk2 = bk * NCH + cp;
#pragma unroll
        for (int f = 0; f < 16; f++) {
            st[f] += g_kvc[((size_t)blk2 * 16 + f) * 64 + tid];
            kc[f] += __ldg(&g_kfc[blk2 * 16 + f]);
        }
    }
    const float4* kfb = reinterpret_cast<const float4*>(&g_kf[(((size_t)bk) * Ss + c * CHUNK) * 16]);
    const float* vb = &g_v[(((size_t)bk) * Ss + c * CHUNK) * 64];
    const int h0 = kvh * 4;
    const float4* qfb[4];
#pragma unroll
    for (int hh = 0; hh < 4; hh++)
        qfb[hh] = reinterpret_cast<const float4*>(&g_qf[(((size_t)(b * Hh + h0 + hh)) * Ss + c * CHUNK) * 16]);
    const size_t abase = ((size_t)b * Ss + c * CHUNK) * Ee + h0 * 64 + tid;

    for (int t = 0; t < CHUNK; t++) {
        float vd = vb[t * 64 + tid];
        float kv[16]; ld16(kv, kfb + t * 4);
#pragma unroll
        for (int f = 0; f < 16; f++) { st[f] += kv[f] * vd; kc[f] += kv[f]; }
#pragma unroll
        for (int hh = 0; hh < 4; hh++) {
            float qv[16]; ld16(qv, qfb[hh] + t * 4);
            float num = 0.f, den = 0.f;
#pragma unroll
            for (int f = 0; f < 16; f++) { num += qv[f] * st[f]; den += qv[f] * kc[f]; }
            float val = num / (den + 1e-6f);
            g_a[abase + (size_t)t * Ee + hh * 64] = __float2half_rn(val);
        }
    }
}

// ---------------- LayerNorm (in-place on d_out) ----------------
__global__ __launch_bounds__(256, 4)
void ln_kernel(float* __restrict__ y, const float* __restrict__ gamma, const float* __restrict__ beta) {
    const int row = blockIdx.x, tid = threadIdx.x;
    float4* yr = reinterpret_cast<float4*>(y + (size_t)row * Ee);
    float4 v = yr[tid];
    float s = v.x + v.y + v.z + v.w;
    float q = v.x * v.x + v.y * v.y + v.z * v.z + v.w * v.w;
    __shared__ float sS[8], sQ[8];
    const int lane = tid & 31, wid = tid >> 5;
#pragma unroll
    for (int off = 16; off; off >>= 1) {
        s += __shfl_xor_sync(0xffffffffu, s, off);
        q += __shfl_xor_sync(0xffffffffu, q, off);
    }
    if (lane == 0) { sS[wid] = s; sQ[wid] = q; }
    __syncthreads();
    if (tid == 0) {
        float ts = 0.f, tq = 0.f;
#pragma unroll
        for (int i = 0; i < 8; i++) { ts += sS[i]; tq += sQ[i]; }
        sS[0] = ts; sQ[0] = tq;
    }
    __syncthreads();
    float mu = sS[0] * (1.f / 1024.f);
    float var = sQ[0] * (1.f / 1024.f) - mu * mu;
    float rstd = rsqrtf(var + 1e-5f);
    const float4 gm = reinterpret_cast<const float4*>(gamma)[tid];
    const float4 bt = reinterpret_cast<const float4*>(beta)[tid];
    float4 o;
    o.x = gm.x * (v.x - mu) * rstd + bt.x;
    o.y = gm.y * (v.y - mu) * rstd + bt.y;
    o.z = gm.z * (v.z - mu) * rstd + bt.z;
    o.w = gm.w * (v.w - mu) * rstd + bt.w;
    yr[tid] = o;
}

// ---------------- launch ----------------
extern "C" void kernel_launch(void* const* d_in, const int* in_sizes, int n_in,
                              void* d_out, int out_size) {
    const float* x    = (const float*)d_in[0];
    const float* ctxW = (const float*)d_in[1];
    const float* ctxb = (const float*)d_in[2];
    const float* qaW  = (const float*)d_in[3];
    const float* qab  = (const float*)d_in[4];
    const float* qbW  = (const float*)d_in[5];
    const float* qbb  = (const float*)d_in[6];
    const float* kaW  = (const float*)d_in[7];
    const float* kab  = (const float*)d_in[8];
    const float* kbW  = (const float*)d_in[9];
    const float* kbb  = (const float*)d_in[10];
    const float* vaW  = (const float*)d_in[11];
    const float* vab  = (const float*)d_in[12];
    const float* vbW  = (const float*)d_in[13];
    const float* vbb  = (const float*)d_in[14];
    const float* qeW  = (const float*)d_in[15];
    const float* qeb  = (const float*)d_in[16];
    const float* vqc  = (const float*)d_in[17];
    const float* ent  = (const float*)d_in[18];
    const float* outW = (const float*)d_in[19];
    const float* outb = (const float*)d_in[20];
    const float* gamma = (const float*)d_in[21];
    const float* beta  = (const float*)d_in[22];
    float* out = (float*)d_out;

    cudaFuncSetAttribute(gemm_tc_kernel, cudaFuncAttributeMaxDynamicSharedMemorySize,
                         NSTAGES * (int)STAGE_BYTES);

    pack_comp_kernel<<<1025, 256>>>(ctxW, qaW, kaW, qbW, kbW, vbW,
                                    ctxb, qab, kab, qbb, kbb, vbb, vab, qeW);
    pack_split_kernel<<<1024, 256>>>(vaW, outW);
    convx_kernel<<<1024, 256>>>(x);

    __half *p_x, *p_W, *p_a, *p_oW;
    float *p_P, *p_bcat;
    cudaGetSymbolAddress((void**)&p_x, g_x);
    cudaGetSymbolAddress((void**)&p_W, g_W);
    cudaGetSymbolAddress((void**)&p_a, g_a);
    cudaGetSymbolAddress((void**)&p_oW, g_oW);
    cudaGetSymbolAddress((void**)&p_P, g_P);
    cudaGetSymbolAddress((void**)&p_bcat, g_bcat);

    dim3 g1(NCAT / 64, NTOK / 256);               // 13 x 32
    gemm_tc_kernel<<<g1, 256, NSTAGES * STAGE_BYTES>>>(NCAT, Ee, p_x, p_W, p_bcat, nullptr, p_P);

    tpa_feat_kernel<<<NTOK, 256>>>(qeb, vqc, ent);

    passA_kernel<<<Bb * KVv * NCH, 64>>>();
    passC_kernel<<<Bb * KVv * NCH, 64>>>();

    dim3 g2(Ee / 64, NTOK / 256);                 // 16 x 32
    gemm_tc_kernel<<<g2, 256, NSTAGES * STAGE_BYTES>>>(Ee, Ee, p_a, p_oW, outb, x, out);

    ln_kernel<<<NTOK, 256>>>(out, gamma, beta);
}

// round 15
// speedup vs baseline: 1.0564x; 1.0564x over previous
#include <cuda_runtime.h>
#include <cuda_fp16.h>
#include <math.h>

#define Bb 4
#define Ss 2048
#define Ee 1024
#define Hh 16
#define KVv 4
#define HDd 64
#define Rr 8
#define CDd 64
#define NQq 8
#define NCH 32
#define CHUNK 64
#define NTOK (Bb*Ss)      // 8192
#define NCAT 832          // aq 64 | kaq 64 | qb 128 | kb 32 | vb 32 | va 512

// ---------------- scratch (device globals; no cudaMalloc allowed) ----------------
// GEMM B operands stored TRANSPOSED [N][K] for cp.async. Single fp16 precision.
__device__ __align__(16) __half g_W[(size_t)NCAT * 1024];
__device__ __align__(16) __half g_oW[(size_t)1024 * 1024];
__device__ __align__(16) __half g_x[(size_t)NTOK * Ee];
__device__ __align__(16) __half g_a[(size_t)NTOK * Ee];
__device__ float g_cw[(size_t)1024 * 320];     // fp32 composite weights [k][n<320]
__device__ float g_bcat[NCAT];
__device__ float g_P[(size_t)NTOK * NCAT];
__device__ float g_v[(size_t)Bb * KVv * Ss * HDd];
__device__ float g_qf[(size_t)Bb * Hh * Ss * 16];
__device__ float g_kf[(size_t)Bb * KVv * Ss * 16];
__device__ float g_kvc[(size_t)Bb * KVv * NCH * 16 * 64];
__device__ float g_kfc[Bb * KVv * NCH * 16];

// ---------------- helpers ----------------
__device__ __forceinline__ void ld16(float* o, const float4* p) {
    float4 a = __ldg(p + 0), b = __ldg(p + 1), c = __ldg(p + 2), d = __ldg(p + 3);
    o[0] = a.x;  o[1] = a.y;  o[2] = a.z;  o[3] = a.w;
    o[4] = b.x;  o[5] = b.y;  o[6] = b.z;  o[7] = b.w;
    o[8] = c.x;  o[9] = c.y;  o[10] = c.z; o[11] = c.w;
    o[12] = d.x; o[13] = d.y; o[14] = d.z; o[15] = d.w;
}

#define MMA_F16(d, a, b0, b1)                                               \
    asm volatile("mma.sync.aligned.m16n8k16.row.col.f32.f16.f16.f32 "       \
                 "{%0,%1,%2,%3}, {%4,%5,%6,%7}, {%8,%9}, {%0,%1,%2,%3};"    \
                 : "+f"(d[0]), "+f"(d[1]), "+f"(d[2]), "+f"(d[3])           \
                 : "r"(a[0]), "r"(a[1]), "r"(a[2]), "r"(a[3]),              \
                   "r"(b0), "r"(b1))

#define LDM4A(rr, addr)                                                     \
    asm volatile("ldmatrix.sync.aligned.m8n8.x4.shared.b16 {%0,%1,%2,%3}, [%4];" \
                 : "=r"((rr)[0]), "=r"((rr)[1]), "=r"((rr)[2]), "=r"((rr)[3]) \
                 : "r"(addr))

// ---------------- K0a: composite weights, fp32, [k][n] (coalesced writes) ----------------
__global__ void pack_comp_kernel(
    const float* __restrict__ ctxW, const float* __restrict__ qaW, const float* __restrict__ kaW,
    const float* __restrict__ qbW,  const float* __restrict__ kbW, const float* __restrict__ vbW,
    const float* __restrict__ ctxb, const float* __restrict__ qab, const float* __restrict__ kab,
    const float* __restrict__ qbb,  const float* __restrict__ kbb, const float* __restrict__ vbb,
    const float* __restrict__ vab,  const float* __restrict__ qeW)
{
    const int k = blockIdx.x;
    const int tid = threadIdx.x;
    if (k < 1024) {
        __shared__ float sA[512], sKA[512], sCtx[64];
        for (int i = tid; i < 512; i += 256) { sA[i] = qaW[(size_t)k * 512 + i]; sKA[i] = kaW[(size_t)k * 512 + i]; }
        if (tid < 64) sCtx[tid] = ctxW[k * 64 + tid];
        __syncthreads();
        for (int n = tid; n < 320; n += 256) {
            float v = 0.f;
            if (n < 64) {
                int r = n >> 3, j = n & 7;
#pragma unroll 8
                for (int d = 0; d < 64; d++) v += sA[r * 64 + d] * __ldg(&qeW[d * 8 + j]);
            } else if (n < 128) {
                int m = n - 64, r = m >> 3, j = m & 7;
#pragma unroll 8
                for (int d = 0; d < 64; d++) v += sKA[r * 64 + d] * __ldg(&qeW[d * 8 + j]);
            } else if (n < 256) {
                int h = n - 128;
#pragma unroll 8
                for (int c = 0; c < 64; c++) v += sCtx[c] * __ldg(&qbW[c * 128 + h]);
            } else if (n < 288) {
                int h = n - 256;
#pragma unroll 8
                for (int c = 0; c < 64; c++) v += sCtx[c] * __ldg(&kbW[c * 32 + h]);
            } else {
                int h = n - 288;
#pragma unroll 8
                for (int c = 0; c < 64; c++) v += sCtx[c] * __ldg(&vbW[c * 32 + h]);
            }
            g_cw[(size_t)k * 320 + n] = v;
        }
    } else {
        for (int n = tid; n < NCAT; n += 256) {
            float v = 0.f;
            if (n < 64) {
                int r = n >> 3, j = n & 7;
                for (int d = 0; d < 64; d++) v += __ldg(&qab[r * 64 + d]) * __ldg(&qeW[d * 8 + j]);
            } else if (n < 128) {
                int m = n - 64, r = m >> 3, j = m & 7;
                for (int d = 0; d < 64; d++) v += __ldg(&kab[r * 64 + d]) * __ldg(&qeW[d * 8 + j]);
            } else if (n < 256) {
                int h = n - 128; v = qbb[h];
                for (int c = 0; c < 64; c++) v += ctxb[c] * __ldg(&qbW[c * 128 + h]);
            } else if (n < 288) {
                int h = n - 256; v = kbb[h];
                for (int c = 0; c < 64; c++) v += ctxb[c] * __ldg(&kbW[c * 32 + h]);
            } else if (n < 320) {
                int h = n - 288; v = vbb[h];
                for (int c = 0; c < 64; c++) v += ctxb[c] * __ldg(&vbW[c * 32 + h]);
            } else {
                v = vab[n - 320];
            }
            g_bcat[n] = v;
        }
    }
}

// ---------------- K0b: weights -> fp16, [n][k] layout ----------------
__global__ void pack_split_kernel(const float* __restrict__ vaW, const float* __restrict__ outW) {
    const size_t totalW = (size_t)NCAT * 1024;
    for (size_t i = blockIdx.x * blockDim.x + threadIdx.x; i < totalW; i += (size_t)gridDim.x * blockDim.x) {
        int k = (int)(i & 1023), n = (int)(i >> 10);
        float v = (n < 320) ? g_cw[(size_t)k * 320 + n]
                            : __ldg(&vaW[(size_t)k * 512 + (n - 320)]);
        g_W[i] = __float2half_rn(v);
    }
    const size_t total2 = (size_t)1024 * 1024;
    for (size_t i = blockIdx.x * blockDim.x + threadIdx.x; i < total2; i += (size_t)gridDim.x * blockDim.x) {
        int k = (int)(i & 1023);
        int n = (int)(i >> 10);
        g_oW[i] = __float2half_rn(__ldg(&outW[(size_t)k * 1024 + n]));
    }
}

// ---------------- K0c: x -> fp16 ----------------
__global__ void convx_kernel(const float* __restrict__ x) {
    const int total4 = NTOK * Ee / 4;
    for (int i = blockIdx.x * blockDim.x + threadIdx.x; i < total4; i += gridDim.x * blockDim.x) {
        float4 v = reinterpret_cast<const float4*>(x)[i];
        __half2 a; a.x = __float2half_rn(v.x); a.y = __float2half_rn(v.y);
        __half2 b; b.x = __float2half_rn(v.z); b.y = __float2half_rn(v.w);
        reinterpret_cast<__half2*>(g_x)[i * 2]     = a;
        reinterpret_cast<__half2*>(g_x)[i * 2 + 1] = b;
    }
}

// ---------------- tensor-core GEMM: fp16, reuse + occupancy balance ----------------
// C[M,N] = A[M,K] @ B^T, A/B fp16, B stored [N][K], fp32 accumulate.
// BM=128, BN=128, BK=64, 256 thr = 8 warps (2M x 4N), warp tile 64M x 32N.
// Per warp-ks: 4 A-ldm4 + 2 B-ldm4 -> 16 MMAs (0.375 ldm4/MMA).
// Stage: A 128x64 (16KB) @0 | B 128x64 (16KB) @16K; 32KB x 3 stages = 96KB, 2 CTA/SM.
// Rows 128B (8 x 16B chunks); swizzle: phys_chunk = ch ^ (row & 7).
#define STAGE_BYTES 32768u
#define NSTAGES 3

__global__ __launch_bounds__(256, 2)
void gemm_tc_kernel(int N, int K,
                    const __half* __restrict__ Ap, const __half* __restrict__ Bp,
                    const float* __restrict__ bias, const float* __restrict__ res,
                    float* __restrict__ C)
{
    extern __shared__ __align__(16) unsigned char dsm[];
    unsigned sbase = (unsigned)__cvta_generic_to_shared(dsm);
    const int bm = blockIdx.y * 128, bn = blockIdx.x * 128;
    const int tid = threadIdx.x, warp = tid >> 5, lane = tid & 31;
    const int wm = (warp >> 2) * 64, wn = (warp & 3) * 32;
    const int r = lane >> 2, cq = (lane & 3) * 2;

    // ---- persistent fill-task state: 8 chunks/thread (2048 total) ----
    const __half* gp[8];
    unsigned doff[8], fsz[8];
#pragma unroll
    for (int w = 0; w < 8; w++) {
        int tsk = tid + w * 256;             // 0..2047 16B-chunks of one stage
        int row, ch;
        unsigned abase;
        const __half* g;
        unsigned s = 16;
        if (tsk < 1024) {                    // A: 128 rows x 8 chunks
            row = tsk >> 3; ch = tsk & 7;
            abase = 0u;
            g = Ap + (size_t)(bm + row) * K + ch * 8;
        } else {                             // B: 128 rows x 8 chunks
            int t2 = tsk - 1024;
            row = t2 >> 3; ch = t2 & 7;
            abase = 16384u;
            int n = bn + row;
            int nc = n < N ? n : 0;
            s = n < N ? 16u : 0u;
            g = Bp + (size_t)nc * K + ch * 8;
        }
        gp[w] = g; fsz[w] = s;
        doff[w] = abase + (unsigned)(row * 128 + ((ch ^ (row & 7)) << 4));
    }

#define FILL_STAGE(ST) do {                                                  \
    _Pragma("unroll")                                                        \
    for (int w = 0; w < 8; w++) {                                            \
        asm volatile("cp.async.cg.shared.global [%0], [%1], 16, %2;"         \
                     :: "r"((ST) + doff[w]), "l"(gp[w]), "r"(fsz[w]));       \
        gp[w] += 64;                                                         \
    }                                                                        \
    asm volatile("cp.async.commit_group;");                                  \
} while (0)

    // ---- fragment base geometry ----
    const int rA = wm + (lane & 15);
    const int rB = wn + (lane & 15);
    const unsigned oAr = (unsigned)(rA * 128);
    const unsigned oBr = 16384u + (unsigned)(rB * 128);
    const unsigned swA = (unsigned)(rA & 7);
    const unsigned swB = (unsigned)(rB & 7);
    const unsigned c0 = (unsigned)(lane >> 4);

    float acc[4][4][4];
#pragma unroll
    for (int mt = 0; mt < 4; mt++)
#pragma unroll
        for (int j = 0; j < 4; j++)
#pragma unroll
            for (int q = 0; q < 4; q++) acc[mt][j][q] = 0.f;

    const int nk = K / 64;
    FILL_STAGE(sbase);
    FILL_STAGE(sbase + STAGE_BYTES);

    for (int kt = 0; kt < nk; kt++) {
        asm volatile("cp.async.wait_group 1;");
        __syncthreads();
        if (kt + 2 < nk) {
            FILL_STAGE(sbase + (unsigned)((kt + 2) % NSTAGES) * STAGE_BYTES);
        } else {
            asm volatile("cp.async.commit_group;");
        }

        const unsigned st = sbase + (unsigned)(kt % NSTAGES) * STAGE_BYTES;
#pragma unroll
        for (int ks = 0; ks < 4; ks++) {
            const unsigned ch = (unsigned)(2 * ks) + c0;
            const unsigned aaddr = st + oAr + ((ch ^ swA) << 4);
            const unsigned baddr = st + oBr + ((ch ^ swB) << 4);
            unsigned ah[4][4];
            LDM4A(ah[0], aaddr);             // rows +16 keep swizzle (16 % 8 == 0)
            LDM4A(ah[1], aaddr + 2048u);
            LDM4A(ah[2], aaddr + 4096u);
            LDM4A(ah[3], aaddr + 6144u);
#pragma unroll
            for (int jj = 0; jj < 2; jj++) {
                unsigned bh[4];
                LDM4A(bh, baddr + (unsigned)jj * 2048u);
#pragma unroll
                for (int sub = 0; sub < 2; sub++)
#pragma unroll
                    for (int mt = 0; mt < 4; mt++)
                        MMA_F16(acc[mt][jj * 2 + sub], ah[mt], bh[sub], bh[2 + sub]);
            }
        }
    }

    // ---- epilogue: + bias (+ residual) ----
#pragma unroll
    for (int mt = 0; mt < 4; mt++) {
        int row0 = bm + wm + mt * 16 + r;
#pragma unroll
        for (int j = 0; j < 4; j++) {
            int col = bn + wn + j * 8 + cq;
            if (col < N) {
                float b0v = bias[col], b1v = bias[col + 1];
                size_t o0 = (size_t)row0 * N + col;
                size_t o1 = (size_t)(row0 + 8) * N + col;
                float v0 = acc[mt][j][0] + b0v, v1 = acc[mt][j][1] + b1v;
                float v2 = acc[mt][j][2] + b0v, v3 = acc[mt][j][3] + b1v;
                if (res) {
                    v0 += res[o0]; v1 += res[o0 + 1];
                    v2 += res[o1]; v3 += res[o1 + 1];
                }
                C[o0] = v0; C[o0 + 1] = v1;
                C[o1] = v2; C[o1 + 1] = v3;
            }
        }
    }
#undef FILL_STAGE
}

// ---------------- K2: v-assembly + quantum features ----------------
// g_P row layout: [aq 0:64 | kaq 64:128 | qb 128:256 | kb 256:288 | vb 288:320 | va 320:832]
__global__ __launch_bounds__(256, 6)
void tpa_feat_kernel(const float* __restrict__ qeb, const float* __restrict__ vqc,
                     const float* __restrict__ ent) {
    __shared__ float sP[NCAT];
    __shared__ float sVQ[48];
    __shared__ float sQEB[8];
    const int token = blockIdx.x;
    const int b = token / Ss, s = token % Ss;
    const int tid = threadIdx.x;

    const float4* p4 = reinterpret_cast<const float4*>(&g_P[(size_t)token * NCAT]);
    if (tid < NCAT / 4) reinterpret_cast<float4*>(sP)[tid] = p4[tid];
    if (tid >= 192 && tid < 240) sVQ[tid - 192] = __ldg(&vqc[tid - 192]);
    if (tid >= 240 && tid < 248) sQEB[tid - 240] = __ldg(&qeb[tid - 240]);
    __syncthreads();

    // v[kv,d] = sum_r va[r,d] * vb[r,kv]
    {
        int kv = tid >> 6, d = tid & 63;
        float av = 0.f;
#pragma unroll
        for (int r = 0; r < 8; r++) av += sP[320 + r * 64 + d] * sP[288 + r * 4 + kv];
        g_v[(((size_t)(b * KVv + kv)) * Ss + s) * 64 + d] = av;
    }

    // quantum features: one thread per (head, qubit), 20 heads x 8 = 160 threads
    const int oct = tid >> 3, j = tid & 7;
    if (oct < 20) {
        const float ev = __ldg(ent);
        float p = sQEB[j];
        if (oct < 16) {
#pragma unroll
            for (int r = 0; r < 8; r++) p += sP[128 + r * 16 + oct] * sP[r * 8 + j];
        } else {
#pragma unroll
            for (int r = 0; r < 8; r++) p += sP[256 + r * 4 + (oct - 16)] * sP[64 + r * 8 + j];
        }
        float f = tanhf(p) * 3.14159265358979323846f;
#pragma unroll
        for (int l = 0; l < 2; l++) {
            float a0 = sVQ[(l * 8 + j) * 3 + 0];
            float a1 = sVQ[(l * 8 + j) * 3 + 1];
            float a2 = sVQ[(l * 8 + j) * 3 + 2];
            float g = cosf(f + a0) * sinf(f + a1) + cosf(f + a2);
            int srcLane = ((tid & 31) & ~7) | ((j + 7) & 7);
            float gp = __shfl_sync(0xffffffffu, g, srcLane);
            f = g * (1.f + ev * gp);
        }
        float cv = cosf(f), sv = sinf(f);
        float nr = cv * cv + sv * sv;
        nr += __shfl_xor_sync(0xffffffffu, nr, 1);
        nr += __shfl_xor_sync(0xffffffffu, nr, 2);
        nr += __shfl_xor_sync(0xffffffffu, nr, 4);
        float inv = 1.f / (sqrtf(nr) + 1e-6f);
        float* dst = oct < 16
            ? &g_qf[(((size_t)(b * Hh + oct)) * Ss + s) * 16]
            : &g_kf[(((size_t)(b * KVv + (oct - 16))) * Ss + s) * 16];
        dst[j]     = cv * inv;
        dst[j + 8] = sv * inv;
    }
}

// ---------------- Pass A: per-chunk sums of kf (x) v and kf ----------------
__global__ __launch_bounds__(64, 8)
void passA_kernel() {
    const int blk = blockIdx.x;            // (b*KV+kv)*NCH + c
    const int c = blk % NCH;
    const int bk = blk / NCH;
    const int tid = threadIdx.x;           // d
    const float4* kfb = reinterpret_cast<const float4*>(&g_kf[(((size_t)bk) * Ss + c * CHUNK) * 16]);
    const float* vb = &g_v[(((size_t)bk) * Ss + c * CHUNK) * 64];
    float acc[16];
#pragma unroll
    for (int f = 0; f < 16; f++) acc[f] = 0.f;
    float kfs = 0.f;
    for (int t = 0; t < CHUNK; t++) {
        float vd = vb[t * 64 + tid];
        float kv[16]; ld16(kv, kfb + t * 4);
#pragma unroll
        for (int f = 0; f < 16; f++) acc[f] += kv[f] * vd;
        if (tid < 16) kfs += __ldg(&g_kf[(((size_t)bk) * Ss + c * CHUNK + t) * 16 + tid]);
    }
#pragma unroll
    for (int f = 0; f < 16; f++) g_kvc[((size_t)blk * 16 + f) * 64 + tid] = acc[f];
    if (tid < 16) g_kfc[blk * 16 + tid] = kfs;
}

// ---------------- Pass C: chunk prefix + within-chunk scan + query eval ----------------
__global__ __launch_bounds__(64, 8)
void passC_kernel() {
    const int blk = blockIdx.x;
    const int c = blk % NCH;
    const int bk = blk / NCH;
    const int b = bk / KVv, kvh = bk % KVv;
    const int tid = threadIdx.x;           // d
    float st[16], kc[16];
#pragma unroll
    for (int f = 0; f < 16; f++) { st[f] = 0.f; kc[f] = 0.f; }
    for (int cp = 0; cp < c; cp++) {
        int blk2 = bk * NCH + cp;
#pragma unroll
        for (int f = 0; f < 16; f++) {
            st[f] += g_kvc[((size_t)blk2 * 16 + f) * 64 + tid];
            kc[f] += __ldg(&g_kfc[blk2 * 16 + f]);
        }
    }
    const float4* kfb = reinterpret_cast<const float4*>(&g_kf[(((size_t)bk) * Ss + c * CHUNK) * 16]);
    const float* vb = &g_v[(((size_t)bk) * Ss + c * CHUNK) * 64];
    const int h0 = kvh * 4;
    const float4* qfb[4];
#pragma unroll
    for (int hh = 0; hh < 4; hh++)
        qfb[hh] = reinterpret_cast<const float4*>(&g_qf[(((size_t)(b * Hh + h0 + hh)) * Ss + c * CHUNK) * 16]);
    const size_t abase = ((size_t)b * Ss + c * CHUNK) * Ee + h0 * 64 + tid;

    for (int t = 0; t < CHUNK; t++) {
        float vd = vb[t * 64 + tid];
        float kv[16]; ld16(kv, kfb + t * 4);
#pragma unroll
        for (int f = 0; f < 16; f++) { st[f] += kv[f] * vd; kc[f] += kv[f]; }
#pragma unroll
        for (int hh = 0; hh < 4; hh++) {
            float qv[16]; ld16(qv, qfb[hh] + t * 4);
            float num = 0.f, den = 0.f;
#pragma unroll
            for (int f = 0; f < 16; f++) { num += qv[f] * st[f]; den += qv[f] * kc[f]; }
            float val = num / (den + 1e-6f);
            g_a[abase + (size_t)t * Ee + hh * 64] = __float2half_rn(val);
        }
    }
}

// ---------------- LayerNorm (in-place on d_out) ----------------
__global__ __launch_bounds__(256, 4)
void ln_kernel(float* __restrict__ y, const float* __restrict__ gamma, const float* __restrict__ beta) {
    const int row = blockIdx.x, tid = threadIdx.x;
    float4* yr = reinterpret_cast<float4*>(y + (size_t)row * Ee);
    float4 v = yr[tid];
    float s = v.x + v.y + v.z + v.w;
    float q = v.x * v.x + v.y * v.y + v.z * v.z + v.w * v.w;
    __shared__ float sS[8], sQ[8];
    const int lane = tid & 31, wid = tid >> 5;
#pragma unroll
    for (int off = 16; off; off >>= 1) {
        s += __shfl_xor_sync(0xffffffffu, s, off);
        q += __shfl_xor_sync(0xffffffffu, q, off);
    }
    if (lane == 0) { sS[wid] = s; sQ[wid] = q; }
    __syncthreads();
    if (tid == 0) {
        float ts = 0.f, tq = 0.f;
#pragma unroll
        for (int i = 0; i < 8; i++) { ts += sS[i]; tq += sQ[i]; }
        sS[0] = ts; sQ[0] = tq;
    }
    __syncthreads();
    float mu = sS[0] * (1.f / 1024.f);
    float var = sQ[0] * (1.f / 1024.f) - mu * mu;
    float rstd = rsqrtf(var + 1e-5f);
    const float4 gm = reinterpret_cast<const float4*>(gamma)[tid];
    const float4 bt = reinterpret_cast<const float4*>(beta)[tid];
    float4 o;
    o.x = gm.x * (v.x - mu) * rstd + bt.x;
    o.y = gm.y * (v.y - mu) * rstd + bt.y;
    o.z = gm.z * (v.z - mu) * rstd + bt.z;
    o.w = gm.w * (v.w - mu) * rstd + bt.w;
    yr[tid] = o;
}

// ---------------- launch ----------------
extern "C" void kernel_launch(void* const* d_in, const int* in_sizes, int n_in,
                              void* d_out, int out_size) {
    const float* x    = (const float*)d_in[0];
    const float* ctxW = (const float*)d_in[1];
    const float* ctxb = (const float*)d_in[2];
    const float* qaW  = (const float*)d_in[3];
    const float* qab  = (const float*)d_in[4];
    const float* qbW  = (const float*)d_in[5];
    const float* qbb  = (const float*)d_in[6];
    const float* kaW  = (const float*)d_in[7];
    const float* kab  = (const float*)d_in[8];
    const float* kbW  = (const float*)d_in[9];
    const float* kbb  = (const float*)d_in[10];
    const float* vaW  = (const float*)d_in[11];
    const float* vab  = (const float*)d_in[12];
    const float* vbW  = (const float*)d_in[13];
    const float* vbb  = (const float*)d_in[14];
    const float* qeW  = (const float*)d_in[15];
    const float* qeb  = (const float*)d_in[16];
    const float* vqc  = (const float*)d_in[17];
    const float* ent  = (const float*)d_in[18];
    const float* outW = (const float*)d_in[19];
    const float* outb = (const float*)d_in[20];
    const float* gamma = (const float*)d_in[21];
    const float* beta  = (const float*)d_in[22];
    float* out = (float*)d_out;

    cudaFuncSetAttribute(gemm_tc_kernel, cudaFuncAttributeMaxDynamicSharedMemorySize,
                         NSTAGES * (int)STAGE_BYTES);

    pack_comp_kernel<<<1025, 256>>>(ctxW, qaW, kaW, qbW, kbW, vbW,
                                    ctxb, qab, kab, qbb, kbb, vbb, vab, qeW);
    pack_split_kernel<<<1024, 256>>>(vaW, outW);
    convx_kernel<<<1024, 256>>>(x);

    __half *p_x, *p_W, *p_a, *p_oW;
    float *p_P, *p_bcat;
    cudaGetSymbolAddress((void**)&p_x, g_x);
    cudaGetSymbolAddress((void**)&p_W, g_W);
    cudaGetSymbolAddress((void**)&p_a, g_a);
    cudaGetSymbolAddress((void**)&p_oW, g_oW);
    cudaGetSymbolAddress((void**)&p_P, g_P);
    cudaGetSymbolAddress((void**)&p_bcat, g_bcat);

    dim3 g1((NCAT + 127) / 128, NTOK / 128);      // 7 x 64
    gemm_tc_kernel<<<g1, 256, NSTAGES * STAGE_BYTES>>>(NCAT, Ee, p_x, p_W, p_bcat, nullptr, p_P);

    tpa_feat_kernel<<<NTOK, 256>>>(qeb, vqc, ent);

    passA_kernel<<<Bb * KVv * NCH, 64>>>();
    passC_kernel<<<Bb * KVv * NCH, 64>>>();

    dim3 g2(Ee / 128, NTOK / 128);                // 8 x 64
    gemm_tc_kernel<<<g2, 256, NSTAGES * STAGE_BYTES>>>(Ee, Ee, p_a, p_oW, outb, x, out);

    ln_kernel<<<NTOK, 256>>>(out, gamma, beta);
}

// round 16
// speedup vs baseline: 1.1643x; 1.1022x over previous
#include <cuda_runtime.h>
#include <cuda_fp16.h>
#include <math.h>

#define Bb 4
#define Ss 2048
#define Ee 1024
#define Hh 16
#define KVv 4
#define HDd 64
#define Rr 8
#define CDd 64
#define NQq 8
#define NCH 32
#define CHUNK 64
#define NTOK (Bb*Ss)      // 8192
#define NCAT 832          // aq 64 | kaq 64 | qb 128 | kb 32 | vb 32 | va 512

// ---------------- scratch (device globals; no cudaMalloc allowed) ----------------
// GEMM B operands stored TRANSPOSED [N][K] for cp.async. Single fp16 precision.
__device__ __align__(16) __half g_W[(size_t)NCAT * 1024];
__device__ __align__(16) __half g_oW[(size_t)1024 * 1024];
__device__ __align__(16) __half g_x[(size_t)NTOK * Ee];
__device__ __align__(16) __half g_a[(size_t)NTOK * Ee];
__device__ float g_cw[(size_t)1024 * 320];     // fp32 composite weights [k][n<320]
__device__ float g_bcat[NCAT];
__device__ float g_P[(size_t)NTOK * NCAT];
__device__ float g_v[(size_t)Bb * KVv * Ss * HDd];
__device__ float g_qf[(size_t)Bb * Hh * Ss * 16];
__device__ float g_kf[(size_t)Bb * KVv * Ss * 16];
__device__ float g_kvc[(size_t)Bb * KVv * NCH * 16 * 64];
__device__ float g_kfc[Bb * KVv * NCH * 16];

// ---------------- helpers ----------------
__device__ __forceinline__ void ld16(float* o, const float4* p) {
    float4 a = __ldg(p + 0), b = __ldg(p + 1), c = __ldg(p + 2), d = __ldg(p + 3);
    o[0] = a.x;  o[1] = a.y;  o[2] = a.z;  o[3] = a.w;
    o[4] = b.x;  o[5] = b.y;  o[6] = b.z;  o[7] = b.w;
    o[8] = c.x;  o[9] = c.y;  o[10] = c.z; o[11] = c.w;
    o[12] = d.x; o[13] = d.y; o[14] = d.z; o[15] = d.w;
}

#define MMA_F16(d, a, b0, b1)                                               \
    asm volatile("mma.sync.aligned.m16n8k16.row.col.f32.f16.f16.f32 "       \
                 "{%0,%1,%2,%3}, {%4,%5,%6,%7}, {%8,%9}, {%0,%1,%2,%3};"    \
                 : "+f"(d[0]), "+f"(d[1]), "+f"(d[2]), "+f"(d[3])           \
                 : "r"(a[0]), "r"(a[1]), "r"(a[2]), "r"(a[3]),              \
                   "r"(b0), "r"(b1))

#define LDM4A(rr, addr)                                                     \
    asm volatile("ldmatrix.sync.aligned.m8n8.x4.shared.b16 {%0,%1,%2,%3}, [%4];" \
                 : "=r"((rr)[0]), "=r"((rr)[1]), "=r"((rr)[2]), "=r"((rr)[3]) \
                 : "r"(addr))

// ---------------- K0a: composite weights, fp32, [k][n] (coalesced writes) ----------------
__global__ void pack_comp_kernel(
    const float* __restrict__ ctxW, const float* __restrict__ qaW, const float* __restrict__ kaW,
    const float* __restrict__ qbW,  const float* __restrict__ kbW, const float* __restrict__ vbW,
    const float* __restrict__ ctxb, const float* __restrict__ qab, const float* __restrict__ kab,
    const float* __restrict__ qbb,  const float* __restrict__ kbb, const float* __restrict__ vbb,
    const float* __restrict__ vab,  const float* __restrict__ qeW)
{
    const int k = blockIdx.x;
    const int tid = threadIdx.x;
    if (k < 1024) {
        __shared__ float sA[512], sKA[512], sCtx[64];
        for (int i = tid; i < 512; i += 256) { sA[i] = qaW[(size_t)k * 512 + i]; sKA[i] = kaW[(size_t)k * 512 + i]; }
        if (tid < 64) sCtx[tid] = ctxW[k * 64 + tid];
        __syncthreads();
        for (int n = tid; n < 320; n += 256) {
            float v = 0.f;
            if (n < 64) {
                int r = n >> 3, j = n & 7;
#pragma unroll 8
                for (int d = 0; d < 64; d++) v += sA[r * 64 + d] * __ldg(&qeW[d * 8 + j]);
            } else if (n < 128) {
                int m = n - 64, r = m >> 3, j = m & 7;
#pragma unroll 8
                for (int d = 0; d < 64; d++) v += sKA[r * 64 + d] * __ldg(&qeW[d * 8 + j]);
            } else if (n < 256) {
                int h = n - 128;
#pragma unroll 8
                for (int c = 0; c < 64; c++) v += sCtx[c] * __ldg(&qbW[c * 128 + h]);
            } else if (n < 288) {
                int h = n - 256;
#pragma unroll 8
                for (int c = 0; c < 64; c++) v += sCtx[c] * __ldg(&kbW[c * 32 + h]);
            } else {
                int h = n - 288;
#pragma unroll 8
                for (int c = 0; c < 64; c++) v += sCtx[c] * __ldg(&vbW[c * 32 + h]);
            }
            g_cw[(size_t)k * 320 + n] = v;
        }
    } else {
        for (int n = tid; n < NCAT; n += 256) {
            float v = 0.f;
            if (n < 64) {
                int r = n >> 3, j = n & 7;
                for (int d = 0; d < 64; d++) v += __ldg(&qab[r * 64 + d]) * __ldg(&qeW[d * 8 + j]);
            } else if (n < 128) {
                int m = n - 64, r = m >> 3, j = m & 7;
                for (int d = 0; d < 64; d++) v += __ldg(&kab[r * 64 + d]) * __ldg(&qeW[d * 8 + j]);
            } else if (n < 256) {
                int h = n - 128; v = qbb[h];
                for (int c = 0; c < 64; c++) v += ctxb[c] * __ldg(&qbW[c * 128 + h]);
            } else if (n < 288) {
                int h = n - 256; v = kbb[h];
                for (int c = 0; c < 64; c++) v += ctxb[c] * __ldg(&kbW[c * 32 + h]);
            } else if (n < 320) {
                int h = n - 288; v = vbb[h];
                for (int c = 0; c < 64; c++) v += ctxb[c] * __ldg(&vbW[c * 32 + h]);
            } else {
                v = vab[n - 320];
            }
            g_bcat[n] = v;
        }
    }
}

// ---------------- K0b: weights -> fp16, [n][k] layout ----------------
__global__ void pack_split_kernel(const float* __restrict__ vaW, const float* __restrict__ outW) {
    const size_t totalW = (size_t)NCAT * 1024;
    for (size_t i = blockIdx.x * blockDim.x + threadIdx.x; i < totalW; i += (size_t)gridDim.x * blockDim.x) {
        int k = (int)(i & 1023), n = (int)(i >> 10);
        float v = (n < 320) ? g_cw[(size_t)k * 320 + n]
                            : __ldg(&vaW[(size_t)k * 512 + (n - 320)]);
        g_W[i] = __float2half_rn(v);
    }
    const size_t total2 = (size_t)1024 * 1024;
    for (size_t i = blockIdx.x * blockDim.x + threadIdx.x; i < total2; i += (size_t)gridDim.x * blockDim.x) {
        int k = (int)(i & 1023);
        int n = (int)(i >> 10);
        g_oW[i] = __float2half_rn(__ldg(&outW[(size_t)k * 1024 + n]));
    }
}

// ---------------- K0c: x -> fp16 ----------------
__global__ void convx_kernel(const float* __restrict__ x) {
    const int total4 = NTOK * Ee / 4;
    for (int i = blockIdx.x * blockDim.x + threadIdx.x; i < total4; i += gridDim.x * blockDim.x) {
        float4 v = reinterpret_cast<const float4*>(x)[i];
        __half2 a; a.x = __float2half_rn(v.x); a.y = __float2half_rn(v.y);
        __half2 b; b.x = __float2half_rn(v.z); b.y = __float2half_rn(v.w);
        reinterpret_cast<__half2*>(g_x)[i * 2]     = a;
        reinterpret_cast<__half2*>(g_x)[i * 2 + 1] = b;
    }
}

// ---------------- tensor-core GEMM (R13 proven config) ----------------
// C[M,N] = A[M,K] @ B^T, A/B fp16, B stored [N][K], fp32 accumulate.
// BM=64, BN=128, BK=64, 256 thr, 3 CTAs/SM.
// Stage: A 64x64 fp16 (8KB) @0 | B 128x64 (16KB) @8K; stage = 24KB x 3 = 72KB.
// Rows are 128B (8 x 16B chunks); swizzle: phys_chunk = ch ^ (row & 7).
#define STAGE_BYTES 24576u

__global__ __launch_bounds__(256, 3)
void gemm_tc_kernel(int N, int K,
                    const __half* __restrict__ Ap, const __half* __restrict__ Bp,
                    const float* __restrict__ bias, const float* __restrict__ res,
                    float* __restrict__ C)
{
    extern __shared__ __align__(16) unsigned char dsm[];
    unsigned sbase = (unsigned)__cvta_generic_to_shared(dsm);
    const int bm = blockIdx.y * 64, bn = blockIdx.x * 128;
    const int tid = threadIdx.x, warp = tid >> 5, lane = tid & 31;
    const int wm = (warp >> 2) * 32, wn = (warp & 3) * 32;
    const int r = lane >> 2, cq = (lane & 3) * 2;

    // ---- persistent fill-task state (pointers advance +64 elems per stage) ----
    const __half* gp[6];
    unsigned doff[6], fsz[6];
#pragma unroll
    for (int w = 0; w < 6; w++) {
        int tsk = tid + w * 256;             // 0..1535 16B-chunks of one stage
        int row, ch;
        unsigned abase;
        const __half* g;
        unsigned s = 16;
        if (tsk < 512) {                     // A: 64 rows x 8 chunks
            row = tsk >> 3; ch = tsk & 7;
            abase = 0u;
            g = Ap + (size_t)(bm + row) * K + ch * 8;
        } else {                             // B: 128 rows x 8 chunks
            int t2 = tsk - 512;
            row = t2 >> 3; ch = t2 & 7;
            abase = 8192u;
            int n = bn + row;
            int nc = n < N ? n : 0;
            s = n < N ? 16u : 0u;
            g = Bp + (size_t)nc * K + ch * 8;
        }
        gp[w] = g; fsz[w] = s;
        doff[w] = abase + (unsigned)(row * 128 + ((ch ^ (row & 7)) << 4));
    }

#define FILL_STAGE(ST) do {                                                  \
    _Pragma("unroll")                                                        \
    for (int w = 0; w < 6; w++) {                                            \
        asm volatile("cp.async.cg.shared.global [%0], [%1], 16, %2;"         \
                     :: "r"((ST) + doff[w]), "l"(gp[w]), "r"(fsz[w]));       \
        gp[w] += 64;                                                         \
    }                                                                        \
    asm volatile("cp.async.commit_group;");                                  \
} while (0)

    // ---- fragment base geometry ----
    const int rA = wm + (lane & 15);
    const int rB = wn + (lane & 15);
    const unsigned oAr = (unsigned)(rA * 128);
    const unsigned oBr = 8192u + (unsigned)(rB * 128);
    const unsigned swA = (unsigned)(rA & 7);
    const unsigned swB = (unsigned)(rB & 7);
    const unsigned c0 = (unsigned)(lane >> 4);

    float acc[2][4][4];
#pragma unroll
    for (int mt = 0; mt < 2; mt++)
#pragma unroll
        for (int j = 0; j < 4; j++)
#pragma unroll
            for (int q = 0; q < 4; q++) acc[mt][j][q] = 0.f;

    const int nk = K / 64;
    FILL_STAGE(sbase);
    FILL_STAGE(sbase + STAGE_BYTES);

    for (int kt = 0; kt < nk; kt++) {
        asm volatile("cp.async.wait_group 1;");
        __syncthreads();
        if (kt + 2 < nk) {
            FILL_STAGE(sbase + (unsigned)((kt + 2) % 3) * STAGE_BYTES);
        } else {
            asm volatile("cp.async.commit_group;");
        }

        const unsigned st = sbase + (unsigned)(kt % 3) * STAGE_BYTES;
#pragma unroll
        for (int ks = 0; ks < 4; ks++) {
            const unsigned ch = (unsigned)(2 * ks) + c0;
            const unsigned aaddr = st + oAr + ((ch ^ swA) << 4);
            const unsigned baddr = st + oBr + ((ch ^ swB) << 4);
            unsigned ah[2][4];
            LDM4A(ah[0], aaddr);             // rows +16 keep swizzle (16 % 8 == 0)
            LDM4A(ah[1], aaddr + 2048u);
#pragma unroll
            for (int jj = 0; jj < 2; jj++) {
                unsigned bh[4];
                LDM4A(bh, baddr + (unsigned)jj * 2048u);
#pragma unroll
                for (int sub = 0; sub < 2; sub++)
#pragma unroll
                    for (int mt = 0; mt < 2; mt++)
                        MMA_F16(acc[mt][jj * 2 + sub], ah[mt], bh[sub], bh[2 + sub]);
            }
        }
    }

    // ---- epilogue: + bias (+ residual) ----
#pragma unroll
    for (int mt = 0; mt < 2; mt++) {
        int row0 = bm + wm + mt * 16 + r;
#pragma unroll
        for (int j = 0; j < 4; j++) {
            int col = bn + wn + j * 8 + cq;
            if (col < N) {
                float b0v = bias[col], b1v = bias[col + 1];
                size_t o0 = (size_t)row0 * N + col;
                size_t o1 = (size_t)(row0 + 8) * N + col;
                float v0 = acc[mt][j][0] + b0v, v1 = acc[mt][j][1] + b1v;
                float v2 = acc[mt][j][2] + b0v, v3 = acc[mt][j][3] + b1v;
                if (res) {
                    v0 += res[o0]; v1 += res[o0 + 1];
                    v2 += res[o1]; v3 += res[o1 + 1];
                }
                C[o0] = v0; C[o0 + 1] = v1;
                C[o1] = v2; C[o1 + 1] = v3;
            }
        }
    }
#undef FILL_STAGE
}

// ---------------- K2: v-assembly + quantum features ----------------
// g_P row layout: [aq 0:64 | kaq 64:128 | qb 128:256 | kb 256:288 | vb 288:320 | va 320:832]
__global__ __launch_bounds__(256, 6)
void tpa_feat_kernel(const float* __restrict__ qeb, const float* __restrict__ vqc,
                     const float* __restrict__ ent) {
    __shared__ float sP[NCAT];
    __shared__ float sVQ[48];
    __shared__ float sQEB[8];
    const int token = blockIdx.x;
    const int b = token / Ss, s = token % Ss;
    const int tid = threadIdx.x;

    const float4* p4 = reinterpret_cast<const float4*>(&g_P[(size_t)token * NCAT]);
    if (tid < NCAT / 4) reinterpret_cast<float4*>(sP)[tid] = p4[tid];
    if (tid >= 192 && tid < 240) sVQ[tid - 192] = __ldg(&vqc[tid - 192]);
    if (tid >= 240 && tid < 248) sQEB[tid - 240] = __ldg(&qeb[tid - 240]);
    __syncthreads();

    // v[kv,d] = sum_r va[r,d] * vb[r,kv]
    {
        int kv = tid >> 6, d = tid & 63;
        float av = 0.f;
#pragma unroll
        for (int r = 0; r < 8; r++) av += sP[320 + r * 64 + d] * sP[288 + r * 4 + kv];
        g_v[(((size_t)(b * KVv + kv)) * Ss + s) * 64 + d] = av;
    }

    // quantum features: one thread per (head, qubit), 20 heads x 8 = 160 threads
    const int oct = tid >> 3, j = tid & 7;
    if (oct < 20) {
        const float ev = __ldg(ent);
        float p = sQEB[j];
        if (oct < 16) {
#pragma unroll
            for (int r = 0; r < 8; r++) p += sP[128 + r * 16 + oct] * sP[r * 8 + j];
        } else {
#pragma unroll
            for (int r = 0; r < 8; r++) p += sP[256 + r * 4 + (oct - 16)] * sP[64 + r * 8 + j];
        }
        float f = tanhf(p) * 3.14159265358979323846f;
#pragma unroll
        for (int l = 0; l < 2; l++) {
            float a0 = sVQ[(l * 8 + j) * 3 + 0];
            float a1 = sVQ[(l * 8 + j) * 3 + 1];
            float a2 = sVQ[(l * 8 + j) * 3 + 2];
            float g = cosf(f + a0) * sinf(f + a1) + cosf(f + a2);
            int srcLane = ((tid & 31) & ~7) | ((j + 7) & 7);
            float gp = __shfl_sync(0xffffffffu, g, srcLane);
            f = g * (1.f + ev * gp);
        }
        float cv = cosf(f), sv = sinf(f);
        float nr = cv * cv + sv * sv;
        nr += __shfl_xor_sync(0xffffffffu, nr, 1);
        nr += __shfl_xor_sync(0xffffffffu, nr, 2);
        nr += __shfl_xor_sync(0xffffffffu, nr, 4);
        float inv = 1.f / (sqrtf(nr) + 1e-6f);
        float* dst = oct < 16
            ? &g_qf[(((size_t)(b * Hh + oct)) * Ss + s) * 16]
            : &g_kf[(((size_t)(b * KVv + (oct - 16))) * Ss + s) * 16];
        dst[j]     = cv * inv;
        dst[j + 8] = sv * inv;
    }
}

// ---------------- Pass A: per-chunk sums, 256 threads = 4 t-groups x 64 d ----------------
__global__ __launch_bounds__(256, 2)
void passA_kernel() {
    const int blk = blockIdx.x;            // (b*KV+kv)*NCH + c
    const int c = blk % NCH;
    const int bk = blk / NCH;
    const int tid = threadIdx.x;
    const int d = tid & 63, tg = tid >> 6;  // 4 t-groups of 16 t's
    const int t0 = tg * 16;
    const float4* kfb = reinterpret_cast<const float4*>(&g_kf[(((size_t)bk) * Ss + c * CHUNK) * 16]);
    const float* vb = &g_v[(((size_t)bk) * Ss + c * CHUNK) * 64];
    float acc[16];
#pragma unroll
    for (int f = 0; f < 16; f++) acc[f] = 0.f;
    float kfs = 0.f;
    for (int t = t0; t < t0 + 16; t++) {
        float vd = vb[t * 64 + d];
        float kv[16]; ld16(kv, kfb + t * 4);
#pragma unroll
        for (int f = 0; f < 16; f++) acc[f] += kv[f] * vd;
        if (d < 16) kfs += __ldg(&g_kf[(((size_t)bk) * Ss + c * CHUNK + t) * 16 + d]);
    }
    __shared__ float sAcc[4][16][64];
    __shared__ float sKs[4][16];
#pragma unroll
    for (int f = 0; f < 16; f++) sAcc[tg][f][d] = acc[f];
    if (d < 16) sKs[tg][d] = kfs;
    __syncthreads();
#pragma unroll
    for (int i = tid; i < 1024; i += 256) {
        int f = i >> 6, dd = i & 63;
        g_kvc[((size_t)blk * 16 + f) * 64 + dd] =
            sAcc[0][f][dd] + sAcc[1][f][dd] + sAcc[2][f][dd] + sAcc[3][f][dd];
    }
    if (tid < 16)
        g_kfc[blk * 16 + tid] = sKs[0][tid] + sKs[1][tid] + sKs[2][tid] + sKs[3][tid];
}

// ---------------- Pass C: scan + query eval, 256 threads = 4 heads x 64 d ----------------
// Scan state replicated across the 4 head-groups (same d => same st/kc); query eval
// for the 4 GQA heads runs fully parallel.
__global__ __launch_bounds__(256, 2)
void passC_kernel() {
    const int blk = blockIdx.x;
    const int c = blk % NCH;
    const int bk = blk / NCH;
    const int b = bk / KVv, kvh = bk % KVv;
    const int tid = threadIdx.x;
    const int d = tid & 63, hh = tid >> 6;  // head within GQA group
    float st[16], kc[16];
#pragma unroll
    for (int f = 0; f < 16; f++) { st[f] = 0.f; kc[f] = 0.f; }
    for (int cp = 0; cp < c; cp++) {
        int blk2 = bk * NCH + cp;
#pragma unroll
        for (int f = 0; f < 16; f++) {
            st[f] += g_kvc[((size_t)blk2 * 16 + f) * 64 + d];
            kc[f] += __ldg(&g_kfc[blk2 * 16 + f]);
        }
    }
    const float4* kfb = reinterpret_cast<const float4*>(&g_kf[(((size_t)bk) * Ss + c * CHUNK) * 16]);
    const float* vb = &g_v[(((size_t)bk) * Ss + c * CHUNK) * 64];
    const int h0 = kvh * 4;
    const float4* qfb =
        reinterpret_cast<const float4*>(&g_qf[(((size_t)(b * Hh + h0 + hh)) * Ss + c * CHUNK) * 16]);
    const size_t abase = ((size_t)b * Ss + c * CHUNK) * Ee + (h0 + hh) * 64 + d;

    for (int t = 0; t < CHUNK; t++) {
        float vd = vb[t * 64 + d];
        float kv[16]; ld16(kv, kfb + t * 4);
#pragma unroll
        for (int f = 0; f < 16; f++) { st[f] += kv[f] * vd; kc[f] += kv[f]; }
        float qv[16]; ld16(qv, qfb + t * 4);
        float num = 0.f, den = 0.f;
#pragma unroll
        for (int f = 0; f < 16; f++) { num += qv[f] * st[f]; den += qv[f] * kc[f]; }
        g_a[abase + (size_t)t * Ee] = __float2half_rn(num / (den + 1e-6f));
    }
}

// ---------------- LayerNorm (in-place on d_out) ----------------
__global__ __launch_bounds__(256, 4)
void ln_kernel(float* __restrict__ y, const float* __restrict__ gamma, const float* __restrict__ beta) {
    const int row = blockIdx.x, tid = threadIdx.x;
    float4* yr = reinterpret_cast<float4*>(y + (size_t)row * Ee);
    float4 v = yr[tid];
    float s = v.x + v.y + v.z + v.w;
    float q = v.x * v.x + v.y * v.y + v.z * v.z + v.w * v.w;
    __shared__ float sS[8], sQ[8];
    const int lane = tid & 31, wid = tid >> 5;
#pragma unroll
    for (int off = 16; off; off >>= 1) {
        s += __shfl_xor_sync(0xffffffffu, s, off);
        q += __shfl_xor_sync(0xffffffffu, q, off);
    }
    if (lane == 0) { sS[wid] = s; sQ[wid] = q; }
    __syncthreads();
    if (tid == 0) {
        float ts = 0.f, tq = 0.f;
#pragma unroll
        for (int i = 0; i < 8; i++) { ts += sS[i]; tq += sQ[i]; }
        sS[0] = ts; sQ[0] = tq;
    }
    __syncthreads();
    float mu = sS[0] * (1.f / 1024.f);
    float var = sQ[0] * (1.f / 1024.f) - mu * mu;
    float rstd = rsqrtf(var + 1e-5f);
    const float4 gm = reinterpret_cast<const float4*>(gamma)[tid];
    const float4 bt = reinterpret_cast<const float4*>(beta)[tid];
    float4 o;
    o.x = gm.x * (v.x - mu) * rstd + bt.x;
    o.y = gm.y * (v.y - mu) * rstd + bt.y;
    o.z = gm.z * (v.z - mu) * rstd + bt.z;
    o.w = gm.w * (v.w - mu) * rstd + bt.w;
    yr[tid] = o;
}

// ---------------- launch ----------------
extern "C" void kernel_launch(void* const* d_in, const int* in_sizes, int n_in,
                              void* d_out, int out_size) {
    const float* x    = (const float*)d_in[0];
    const float* ctxW = (const float*)d_in[1];
    const float* ctxb = (const float*)d_in[2];
    const float* qaW  = (const float*)d_in[3];
    const float* qab  = (const float*)d_in[4];
    const float* qbW  = (const float*)d_in[5];
    const float* qbb  = (const float*)d_in[6];
    const float* kaW  = (const float*)d_in[7];
    const float* kab  = (const float*)d_in[8];
    const float* kbW  = (const float*)d_in[9];
    const float* kbb  = (const float*)d_in[10];
    const float* vaW  = (const float*)d_in[11];
    const float* vab  = (const float*)d_in[12];
    const float* vbW  = (const float*)d_in[13];
    const float* vbb  = (const float*)d_in[14];
    const float* qeW  = (const float*)d_in[15];
    const float* qeb  = (const float*)d_in[16];
    const float* vqc  = (const float*)d_in[17];
    const float* ent  = (const float*)d_in[18];
    const float* outW = (const float*)d_in[19];
    const float* outb = (const float*)d_in[20];
    const float* gamma = (const float*)d_in[21];
    const float* beta  = (const float*)d_in[22];
    float* out = (float*)d_out;

    cudaFuncSetAttribute(gemm_tc_kernel, cudaFuncAttributeMaxDynamicSharedMemorySize,
                         3 * (int)STAGE_BYTES);

    pack_comp_kernel<<<1025, 256>>>(ctxW, qaW, kaW, qbW, kbW, vbW,
                                    ctxb, qab, kab, qbb, kbb, vbb, vab, qeW);
    pack_split_kernel<<<1024, 256>>>(vaW, outW);
    convx_kernel<<<1024, 256>>>(x);

    __half *p_x, *p_W, *p_a, *p_oW;
    float *p_P, *p_bcat;
    cudaGetSymbolAddress((void**)&p_x, g_x);
    cudaGetSymbolAddress((void**)&p_W, g_W);
    cudaGetSymbolAddress((void**)&p_a, g_a);
    cudaGetSymbolAddress((void**)&p_oW, g_oW);
    cudaGetSymbolAddress((void**)&p_P, g_P);
    cudaGetSymbolAddress((void**)&p_bcat, g_bcat);

    dim3 g1((NCAT + 127) / 128, NTOK / 64);       // 7 x 128
    gemm_tc_kernel<<<g1, 256, 3 * STAGE_BYTES>>>(NCAT, Ee, p_x, p_W, p_bcat, nullptr, p_P);

    tpa_feat_kernel<<<NTOK, 256>>>(qeb, vqc, ent);

    passA_kernel<<<Bb * KVv * NCH, 256>>>();
    passC_kernel<<<Bb * KVv * NCH, 256>>>();

    dim3 g2(Ee / 128, NTOK / 64);                 // 8 x 128
    gemm_tc_kernel<<<g2, 256, 3 * STAGE_BYTES>>>(Ee, Ee, p_a, p_oW, outb, x, out);

    ln_kernel<<<NTOK, 256>>>(out, gamma, beta);
}

// round 17
// speedup vs baseline: 1.1729x; 1.0074x over previous
#include <cuda_runtime.h>
#include <cuda_fp16.h>
#include <math.h>

#define Bb 4
#define Ss 2048
#define Ee 1024
#define Hh 16
#define KVv 4
#define HDd 64
#define Rr 8
#define CDd 64
#define NQq 8
#define NCH 32
#define CHUNK 64
#define NTOK (Bb*Ss)      // 8192
#define NCAT 832          // aq 64 | kaq 64 | qb 128 | kb 32 | vb 32 | va 512

// ---------------- scratch (device globals; no cudaMalloc allowed) ----------------
// GEMM B operands stored TRANSPOSED [N][K] for cp.async. Single fp16 precision.
__device__ __align__(16) __half g_W[(size_t)NCAT * 1024];
__device__ __align__(16) __half g_oW[(size_t)1024 * 1024];
__device__ __align__(16) __half g_x[(size_t)NTOK * Ee];
__device__ __align__(16) __half g_a[(size_t)NTOK * Ee];
__device__ float g_cw[(size_t)1024 * 320];     // fp32 composite weights [k][n<320]
__device__ float g_bcat[NCAT];
__device__ float g_P[(size_t)NTOK * NCAT];
__device__ float g_v[(size_t)Bb * KVv * Ss * HDd];
__device__ float g_qf[(size_t)Bb * Hh * Ss * 16];
__device__ float g_kf[(size_t)Bb * KVv * Ss * 16];
__device__ float g_kvc[(size_t)Bb * KVv * NCH * 16 * 64];
__device__ float g_kfc[Bb * KVv * NCH * 16];

// ---------------- helpers ----------------
__device__ __forceinline__ void ld16(float* o, const float4* p) {
    float4 a = __ldg(p + 0), b = __ldg(p + 1), c = __ldg(p + 2), d = __ldg(p + 3);
    o[0] = a.x;  o[1] = a.y;  o[2] = a.z;  o[3] = a.w;
    o[4] = b.x;  o[5] = b.y;  o[6] = b.z;  o[7] = b.w;
    o[8] = c.x;  o[9] = c.y;  o[10] = c.z; o[11] = c.w;
    o[12] = d.x; o[13] = d.y; o[14] = d.z; o[15] = d.w;
}

#define MMA_F16(d, a, b0, b1)                                               \
    asm volatile("mma.sync.aligned.m16n8k16.row.col.f32.f16.f16.f32 "       \
                 "{%0,%1,%2,%3}, {%4,%5,%6,%7}, {%8,%9}, {%0,%1,%2,%3};"    \
                 : "+f"(d[0]), "+f"(d[1]), "+f"(d[2]), "+f"(d[3])           \
                 : "r"(a[0]), "r"(a[1]), "r"(a[2]), "r"(a[3]),              \
                   "r"(b0), "r"(b1))

#define LDM4A(rr, addr)                                                     \
    asm volatile("ldmatrix.sync.aligned.m8n8.x4.shared.b16 {%0,%1,%2,%3}, [%4];" \
                 : "=r"((rr)[0]), "=r"((rr)[1]), "=r"((rr)[2]), "=r"((rr)[3]) \
                 : "r"(addr))

// ---------------- K0a: composite weights, fp32, [k][n] (coalesced writes) ----------------
__global__ void pack_comp_kernel(
    const float* __restrict__ ctxW, const float* __restrict__ qaW, const float* __restrict__ kaW,
    const float* __restrict__ qbW,  const float* __restrict__ kbW, const float* __restrict__ vbW,
    const float* __restrict__ ctxb, const float* __restrict__ qab, const float* __restrict__ kab,
    const float* __restrict__ qbb,  const float* __restrict__ kbb, const float* __restrict__ vbb,
    const float* __restrict__ vab,  const float* __restrict__ qeW)
{
    const int k = blockIdx.x;
    const int tid = threadIdx.x;
    if (k < 1024) {
        __shared__ float sA[512], sKA[512], sCtx[64];
        for (int i = tid; i < 512; i += 256) { sA[i] = qaW[(size_t)k * 512 + i]; sKA[i] = kaW[(size_t)k * 512 + i]; }
        if (tid < 64) sCtx[tid] = ctxW[k * 64 + tid];
        __syncthreads();
        for (int n = tid; n < 320; n += 256) {
            float v = 0.f;
            if (n < 64) {
                int r = n >> 3, j = n & 7;
#pragma unroll 8
                for (int d = 0; d < 64; d++) v += sA[r * 64 + d] * __ldg(&qeW[d * 8 + j]);
            } else if (n < 128) {
                int m = n - 64, r = m >> 3, j = m & 7;
#pragma unroll 8
                for (int d = 0; d < 64; d++) v += sKA[r * 64 + d] * __ldg(&qeW[d * 8 + j]);
            } else if (n < 256) {
                int h = n - 128;
#pragma unroll 8
                for (int c = 0; c < 64; c++) v += sCtx[c] * __ldg(&qbW[c * 128 + h]);
            } else if (n < 288) {
                int h = n - 256;
#pragma unroll 8
                for (int c = 0; c < 64; c++) v += sCtx[c] * __ldg(&kbW[c * 32 + h]);
            } else {
                int h = n - 288;
#pragma unroll 8
                for (int c = 0; c < 64; c++) v += sCtx[c] * __ldg(&vbW[c * 32 + h]);
            }
            g_cw[(size_t)k * 320 + n] = v;
        }
    } else {
        for (int n = tid; n < NCAT; n += 256) {
            float v = 0.f;
            if (n < 64) {
                int r = n >> 3, j = n & 7;
                for (int d = 0; d < 64; d++) v += __ldg(&qab[r * 64 + d]) * __ldg(&qeW[d * 8 + j]);
            } else if (n < 128) {
                int m = n - 64, r = m >> 3, j = m & 7;
                for (int d = 0; d < 64; d++) v += __ldg(&kab[r * 64 + d]) * __ldg(&qeW[d * 8 + j]);
            } else if (n < 256) {
                int h = n - 128; v = qbb[h];
                for (int c = 0; c < 64; c++) v += ctxb[c] * __ldg(&qbW[c * 128 + h]);
            } else if (n < 288) {
                int h = n - 256; v = kbb[h];
                for (int c = 0; c < 64; c++) v += ctxb[c] * __ldg(&kbW[c * 32 + h]);
            } else if (n < 320) {
                int h = n - 288; v = vbb[h];
                for (int c = 0; c < 64; c++) v += ctxb[c] * __ldg(&vbW[c * 32 + h]);
            } else {
                v = vab[n - 320];
            }
            g_bcat[n] = v;
        }
    }
}

// ---------------- K0b: weights -> fp16 [n][k] via smem tiled transpose ----------------
// Both reads (n-fastest) and writes (k-fastest) fully coalesced; 33-wide rows
// avoid bank conflicts. n=320 source boundary is a multiple of 32 => each tile
// is single-source. Tiles: W = 32(k) x 26(n) = 832, oW = 32 x 32 = 1024.
__global__ __launch_bounds__(256)
void pack_split_kernel(const float* __restrict__ vaW, const float* __restrict__ outW) {
    __shared__ float tile[32][33];
    const int bid = blockIdx.x;
    const int tid = threadIdx.x;
    if (bid < 832) {
        const int kt = bid & 31, nt = bid >> 5;   // 32 k-tiles x 26 n-tiles
        const int k0 = kt * 32, n0 = nt * 32;
        if (n0 < 320) {
            for (int i = tid; i < 1024; i += 256) {
                int dk = i >> 5, dn = i & 31;
                tile[dk][dn] = g_cw[(size_t)(k0 + dk) * 320 + n0 + dn];
            }
        } else {
            const int nv0 = n0 - 320;
            for (int i = tid; i < 1024; i += 256) {
                int dk = i >> 5, dn = i & 31;
                tile[dk][dn] = __ldg(&vaW[(size_t)(k0 + dk) * 512 + nv0 + dn]);
            }
        }
        __syncthreads();
        for (int i = tid; i < 1024; i += 256) {
            int dn = i >> 5, dk = i & 31;
            g_W[(size_t)(n0 + dn) * 1024 + k0 + dk] = __float2half_rn(tile[dk][dn]);
        }
    } else {
        const int b2 = bid - 832;
        const int kt = b2 & 31, nt = b2 >> 5;     // 32 x 32 tiles
        const int k0 = kt * 32, n0 = nt * 32;
        for (int i = tid; i < 1024; i += 256) {
            int dk = i >> 5, dn = i & 31;
            tile[dk][dn] = __ldg(&outW[(size_t)(k0 + dk) * 1024 + n0 + dn]);
        }
        __syncthreads();
        for (int i = tid; i < 1024; i += 256) {
            int dn = i >> 5, dk = i & 31;
            g_oW[(size_t)(n0 + dn) * 1024 + k0 + dk] = __float2half_rn(tile[dk][dn]);
        }
    }
}

// ---------------- K0c: x -> fp16 ----------------
__global__ void convx_kernel(const float* __restrict__ x) {
    const int total4 = NTOK * Ee / 4;
    for (int i = blockIdx.x * blockDim.x + threadIdx.x; i < total4; i += gridDim.x * blockDim.x) {
        float4 v = reinterpret_cast<const float4*>(x)[i];
        __half2 a; a.x = __float2half_rn(v.x); a.y = __float2half_rn(v.y);
        __half2 b; b.x = __float2half_rn(v.z); b.y = __float2half_rn(v.w);
        reinterpret_cast<__half2*>(g_x)[i * 2]     = a;
        reinterpret_cast<__half2*>(g_x)[i * 2 + 1] = b;
    }
}

// ---------------- tensor-core GEMM (proven config) ----------------
// C[M,N] = A[M,K] @ B^T, A/B fp16, B stored [N][K], fp32 accumulate.
// BM=64, BN=128, BK=64, 256 thr, 3 CTAs/SM.
// Stage: A 64x64 fp16 (8KB) @0 | B 128x64 (16KB) @8K; stage = 24KB x 3 = 72KB.
// Rows are 128B (8 x 16B chunks); swizzle: phys_chunk = ch ^ (row & 7).
#define STAGE_BYTES 24576u

__global__ __launch_bounds__(256, 3)
void gemm_tc_kernel(int N, int K,
                    const __half* __restrict__ Ap, const __half* __restrict__ Bp,
                    const float* __restrict__ bias, const float* __restrict__ res,
                    float* __restrict__ C)
{
    extern __shared__ __align__(16) unsigned char dsm[];
    unsigned sbase = (unsigned)__cvta_generic_to_shared(dsm);
    const int bm = blockIdx.y * 64, bn = blockIdx.x * 128;
    const int tid = threadIdx.x, warp = tid >> 5, lane = tid & 31;
    const int wm = (warp >> 2) * 32, wn = (warp & 3) * 32;
    const int r = lane >> 2, cq = (lane & 3) * 2;

    // ---- persistent fill-task state (pointers advance +64 elems per stage) ----
    const __half* gp[6];
    unsigned doff[6], fsz[6];
#pragma unroll
    for (int w = 0; w < 6; w++) {
        int tsk = tid + w * 256;             // 0..1535 16B-chunks of one stage
        int row, ch;
        unsigned abase;
        const __half* g;
        unsigned s = 16;
        if (tsk < 512) {                     // A: 64 rows x 8 chunks
            row = tsk >> 3; ch = tsk & 7;
            abase = 0u;
            g = Ap + (size_t)(bm + row) * K + ch * 8;
        } else {                             // B: 128 rows x 8 chunks
            int t2 = tsk - 512;
            row = t2 >> 3; ch = t2 & 7;
            abase = 8192u;
            int n = bn + row;
            int nc = n < N ? n : 0;
            s = n < N ? 16u : 0u;
            g = Bp + (size_t)nc * K + ch * 8;
        }
        gp[w] = g; fsz[w] = s;
        doff[w] = abase + (unsigned)(row * 128 + ((ch ^ (row & 7)) << 4));
    }

#define FILL_STAGE(ST) do {                                                  \
    _Pragma("unroll")                                                        \
    for (int w = 0; w < 6; w++) {                                            \
        asm volatile("cp.async.cg.shared.global [%0], [%1], 16, %2;"         \
                     :: "r"((ST) + doff[w]), "l"(gp[w]), "r"(fsz[w]));       \
        gp[w] += 64;                                                         \
    }                                                                        \
    asm volatile("cp.async.commit_group;");                                  \
} while (0)

    // ---- fragment base geometry ----
    const int rA = wm + (lane & 15);
    const int rB = wn + (lane & 15);
    const unsigned oAr = (unsigned)(rA * 128);
    const unsigned oBr = 8192u + (unsigned)(rB * 128);
    const unsigned swA = (unsigned)(rA & 7);
    const unsigned swB = (unsigned)(rB & 7);
    const unsigned c0 = (unsigned)(lane >> 4);

    float acc[2][4][4];
#pragma unroll
    for (int mt = 0; mt < 2; mt++)
#pragma unroll
        for (int j = 0; j < 4; j++)
#pragma unroll
            for (int q = 0; q < 4; q++) acc[mt][j][q] = 0.f;

    const int nk = K / 64;
    FILL_STAGE(sbase);
    FILL_STAGE(sbase + STAGE_BYTES);

    for (int kt = 0; kt < nk; kt++) {
        asm volatile("cp.async.wait_group 1;");
        __syncthreads();
        if (kt + 2 < nk) {
            FILL_STAGE(sbase + (unsigned)((kt + 2) % 3) * STAGE_BYTES);
        } else {
            asm volatile("cp.async.commit_group;");
        }

        const unsigned st = sbase + (unsigned)(kt % 3) * STAGE_BYTES;
#pragma unroll
        for (int ks = 0; ks < 4; ks++) {
            const unsigned ch = (unsigned)(2 * ks) + c0;
            const unsigned aaddr = st + oAr + ((ch ^ swA) << 4);
            const unsigned baddr = st + oBr + ((ch ^ swB) << 4);
            unsigned ah[2][4];
            LDM4A(ah[0], aaddr);             // rows +16 keep swizzle (16 % 8 == 0)
            LDM4A(ah[1], aaddr + 2048u);
#pragma unroll
            for (int jj = 0; jj < 2; jj++) {
                unsigned bh[4];
                LDM4A(bh, baddr + (unsigned)jj * 2048u);
#pragma unroll
                for (int sub = 0; sub < 2; sub++)
#pragma unroll
                    for (int mt = 0; mt < 2; mt++)
                        MMA_F16(acc[mt][jj * 2 + sub], ah[mt], bh[sub], bh[2 + sub]);
            }
        }
    }

    // ---- epilogue: + bias (+ residual) ----
#pragma unroll
    for (int mt = 0; mt < 2; mt++) {
        int row0 = bm + wm + mt * 16 + r;
#pragma unroll
        for (int j = 0; j < 4; j++) {
            int col = bn + wn + j * 8 + cq;
            if (col < N) {
                float b0v = bias[col], b1v = bias[col + 1];
                size_t o0 = (size_t)row0 * N + col;
                size_t o1 = (size_t)(row0 + 8) * N + col;
                float v0 = acc[mt][j][0] + b0v, v1 = acc[mt][j][1] + b1v;
                float v2 = acc[mt][j][2] + b0v, v3 = acc[mt][j][3] + b1v;
                if (res) {
                    v0 += res[o0]; v1 += res[o0 + 1];
                    v2 += res[o1]; v3 += res[o1 + 1];
                }
                C[o0] = v0; C[o0 + 1] = v1;
                C[o1] = v2; C[o1 + 1] = v3;
            }
        }
    }
#undef FILL_STAGE
}

// ---------------- K2: v-assembly + quantum features ----------------
// g_P row layout: [aq 0:64 | kaq 64:128 | qb 128:256 | kb 256:288 | vb 288:320 | va 320:832]
__global__ __launch_bounds__(256, 6)
void tpa_feat_kernel(const float* __restrict__ qeb, const float* __restrict__ vqc,
                     const float* __restrict__ ent) {
    __shared__ float sP[NCAT];
    __shared__ float sVQ[48];
    __shared__ float sQEB[8];
    const int token = blockIdx.x;
    const int b = token / Ss, s = token % Ss;
    const int tid = threadIdx.x;

    const float4* p4 = reinterpret_cast<const float4*>(&g_P[(size_t)token * NCAT]);
    if (tid < NCAT / 4) reinterpret_cast<float4*>(sP)[tid] = p4[tid];
    if (tid >= 192 && tid < 240) sVQ[tid - 192] = __ldg(&vqc[tid - 192]);
    if (tid >= 240 && tid < 248) sQEB[tid - 240] = __ldg(&qeb[tid - 240]);
    __syncthreads();

    // v[kv,d] = sum_r va[r,d] * vb[r,kv]
    {
        int kv = tid >> 6, d = tid & 63;
        float av = 0.f;
#pragma unroll
        for (int r = 0; r < 8; r++) av += sP[320 + r * 64 + d] * sP[288 + r * 4 + kv];
        g_v[(((size_t)(b * KVv + kv)) * Ss + s) * 64 + d] = av;
    }

    // quantum features: one thread per (head, qubit), 20 heads x 8 = 160 threads
    const int oct = tid >> 3, j = tid & 7;
    if (oct < 20) {
        const float ev = __ldg(ent);
        float p = sQEB[j];
        if (oct < 16) {
#pragma unroll
            for (int r = 0; r < 8; r++) p += sP[128 + r * 16 + oct] * sP[r * 8 + j];
        } else {
#pragma unroll
            for (int r = 0; r < 8; r++) p += sP[256 + r * 4 + (oct - 16)] * sP[64 + r * 8 + j];
        }
        float f = tanhf(p) * 3.14159265358979323846f;
#pragma unroll
        for (int l = 0; l < 2; l++) {
            float a0 = sVQ[(l * 8 + j) * 3 + 0];
            float a1 = sVQ[(l * 8 + j) * 3 + 1];
            float a2 = sVQ[(l * 8 + j) * 3 + 2];
            float g = cosf(f + a0) * sinf(f + a1) + cosf(f + a2);
            int srcLane = ((tid & 31) & ~7) | ((j + 7) & 7);
            float gp = __shfl_sync(0xffffffffu, g, srcLane);
            f = g * (1.f + ev * gp);
        }
        float cv = cosf(f), sv = sinf(f);
        float nr = cv * cv + sv * sv;
        nr += __shfl_xor_sync(0xffffffffu, nr, 1);
        nr += __shfl_xor_sync(0xffffffffu, nr, 2);
        nr += __shfl_xor_sync(0xffffffffu, nr, 4);
        float inv = 1.f / (sqrtf(nr) + 1e-6f);
        float* dst = oct < 16
            ? &g_qf[(((size_t)(b * Hh + oct)) * Ss + s) * 16]
            : &g_kf[(((size_t)(b * KVv + (oct - 16))) * Ss + s) * 16];
        dst[j]     = cv * inv;
        dst[j + 8] = sv * inv;
    }
}

// ---------------- Pass A: per-chunk sums, 256 threads = 4 t-groups x 64 d ----------------
__global__ __launch_bounds__(256, 2)
void passA_kernel() {
    const int blk = blockIdx.x;            // (b*KV+kv)*NCH + c
    const int c = blk % NCH;
    const int bk = blk / NCH;
    const int tid = threadIdx.x;
    const int d = tid & 63, tg = tid >> 6;  // 4 t-groups of 16 t's
    const int t0 = tg * 16;
    const float4* kfb = reinterpret_cast<const float4*>(&g_kf[(((size_t)bk) * Ss + c * CHUNK) * 16]);
    const float* vb = &g_v[(((size_t)bk) * Ss + c * CHUNK) * 64];
    float acc[16];
#pragma unroll
    for (int f = 0; f < 16; f++) acc[f] = 0.f;
    float kfs = 0.f;
    for (int t = t0; t < t0 + 16; t++) {
        float vd = vb[t * 64 + d];
        float kv[16]; ld16(kv, kfb + t * 4);
#pragma unroll
        for (int f = 0; f < 16; f++) acc[f] += kv[f] * vd;
        if (d < 16) kfs += __ldg(&g_kf[(((size_t)bk) * Ss + c * CHUNK + t) * 16 + d]);
    }
    __shared__ float sAcc[4][16][64];
    __shared__ float sKs[4][16];
#pragma unroll
    for (int f = 0; f < 16; f++) sAcc[tg][f][d] = acc[f];
    if (d < 16) sKs[tg][d] = kfs;
    __syncthreads();
#pragma unroll
    for (int i = tid; i < 1024; i += 256) {
        int f = i >> 6, dd = i & 63;
        g_kvc[((size_t)blk * 16 + f) * 64 + dd] =
            sAcc[0][f][dd] + sAcc[1][f][dd] + sAcc[2][f][dd] + sAcc[3][f][dd];
    }
    if (tid < 16)
        g_kfc[blk * 16 + tid] = sKs[0][tid] + sKs[1][tid] + sKs[2][tid] + sKs[3][tid];
}

// ---------------- Pass C: scan + query eval, 256 threads = 4 heads x 64 d ----------------
// Scan state replicated across the 4 head-groups (same d => same st/kc); query eval
// for the 4 GQA heads runs fully parallel.
__global__ __launch_bounds__(256, 2)
void passC_kernel() {
    const int blk = blockIdx.x;
    const int c = blk % NCH;
    const int bk = blk / NCH;
    const int b = bk / KVv, kvh = bk % KVv;
    const int tid = threadIdx.x;
    const int d = tid & 63, hh = tid >> 6;  // head within GQA group
    float st[16], kc[16];
#pragma unroll
    for (int f = 0; f < 16; f++) { st[f] = 0.f; kc[f] = 0.f; }
    for (int cp = 0; cp < c; cp++) {
        int blk2 = bk * NCH + cp;
#pragma unroll
        for (int f = 0; f < 16; f++) {
            st[f] += g_kvc[((size_t)blk2 * 16 + f) * 64 + d];
            kc[f] += __ldg(&g_kfc[blk2 * 16 + f]);
        }
    }
    const float4* kfb = reinterpret_cast<const float4*>(&g_kf[(((size_t)bk) * Ss + c * CHUNK) * 16]);
    const float* vb = &g_v[(((size_t)bk) * Ss + c * CHUNK) * 64];
    const int h0 = kvh * 4;
    const float4* qfb =
        reinterpret_cast<const float4*>(&g_qf[(((size_t)(b * Hh + h0 + hh)) * Ss + c * CHUNK) * 16]);
    const size_t abase = ((size_t)b * Ss + c * CHUNK) * Ee + (h0 + hh) * 64 + d;

    for (int t = 0; t < CHUNK; t++) {
        float vd = vb[t * 64 + d];
        float kv[16]; ld16(kv, kfb + t * 4);
#pragma unroll
        for (int f = 0; f < 16; f++) { st[f] += kv[f] * vd; kc[f] += kv[f]; }
        float qv[16]; ld16(qv, qfb + t * 4);
        float num = 0.f, den = 0.f;
#pragma unroll
        for (int f = 0; f < 16; f++) { num += qv[f] * st[f]; den += qv[f] * kc[f]; }
        g_a[abase + (size_t)t * Ee] = __float2half_rn(num / (den + 1e-6f));
    }
}

// ---------------- LayerNorm (in-place on d_out) ----------------
__global__ __launch_bounds__(256, 4)
void ln_kernel(float* __restrict__ y, const float* __restrict__ gamma, const float* __restrict__ beta) {
    const int row = blockIdx.x, tid = threadIdx.x;
    float4* yr = reinterpret_cast<float4*>(y + (size_t)row * Ee);
    float4 v = yr[tid];
    float s = v.x + v.y + v.z + v.w;
    float q = v.x * v.x + v.y * v.y + v.z * v.z + v.w * v.w;
    __shared__ float sS[8], sQ[8];
    const int lane = tid & 31, wid = tid >> 5;
#pragma unroll
    for (int off = 16; off; off >>= 1) {
        s += __shfl_xor_sync(0xffffffffu, s, off);
        q += __shfl_xor_sync(0xffffffffu, q, off);
    }
    if (lane == 0) { sS[wid] = s; sQ[wid] = q; }
    __syncthreads();
    if (tid == 0) {
        float ts = 0.f, tq = 0.f;
#pragma unroll
        for (int i = 0; i < 8; i++) { ts += sS[i]; tq += sQ[i]; }
        sS[0] = ts; sQ[0] = tq;
    }
    __syncthreads();
    float mu = sS[0] * (1.f / 1024.f);
    float var = sQ[0] * (1.f / 1024.f) - mu * mu;
    float rstd = rsqrtf(var + 1e-5f);
    const float4 gm = reinterpret_cast<const float4*>(gamma)[tid];
    const float4 bt = reinterpret_cast<const float4*>(beta)[tid];
    float4 o;
    o.x = gm.x * (v.x - mu) * rstd + bt.x;
    o.y = gm.y * (v.y - mu) * rstd + bt.y;
    o.z = gm.z * (v.z - mu) * rstd + bt.z;
    o.w = gm.w * (v.w - mu) * rstd + bt.w;
    yr[tid] = o;
}

// ---------------- launch ----------------
extern "C" void kernel_launch(void* const* d_in, const int* in_sizes, int n_in,
                              void* d_out, int out_size) {
    const float* x    = (const float*)d_in[0];
    const float* ctxW = (const float*)d_in[1];
    const float* ctxb = (const float*)d_in[2];
    const float* qaW  = (const float*)d_in[3];
    const float* qab  = (const float*)d_in[4];
    const float* qbW  = (const float*)d_in[5];
    const float* qbb  = (const float*)d_in[6];
    const float* kaW  = (const float*)d_in[7];
    const float* kab  = (const float*)d_in[8];
    const float* kbW  = (const float*)d_in[9];
    const float* kbb  = (const float*)d_in[10];
    const float* vaW  = (const float*)d_in[11];
    const float* vab  = (const float*)d_in[12];
    const float* vbW  = (const float*)d_in[13];
    const float* vbb  = (const float*)d_in[14];
    const float* qeW  = (const float*)d_in[15];
    const float* qeb  = (const float*)d_in[16];
    const float* vqc  = (const float*)d_in[17];
    const float* ent  = (const float*)d_in[18];
    const float* outW = (const float*)d_in[19];
    const float* outb = (const float*)d_in[20];
    const float* gamma = (const float*)d_in[21];
    const float* beta  = (const float*)d_in[22];
    float* out = (float*)d_out;

    cudaFuncSetAttribute(gemm_tc_kernel, cudaFuncAttributeMaxDynamicSharedMemorySize,
                         3 * (int)STAGE_BYTES);

    pack_comp_kernel<<<1025, 256>>>(ctxW, qaW, kaW, qbW, kbW, vbW,
                                    ctxb, qab, kab, qbb, kbb, vbb, vab, qeW);
    pack_split_kernel<<<1856, 256>>>(vaW, outW);
    convx_kernel<<<1024, 256>>>(x);

    __half *p_x, *p_W, *p_a, *p_oW;
    float *p_P, *p_bcat;
    cudaGetSymbolAddress((void**)&p_x, g_x);
    cudaGetSymbolAddress((void**)&p_W, g_W);
    cudaGetSymbolAddress((void**)&p_a, g_a);
    cudaGetSymbolAddress((void**)&p_oW, g_oW);
    cudaGetSymbolAddress((void**)&p_P, g_P);
    cudaGetSymbolAddress((void**)&p_bcat, g_bcat);

    dim3 g1((NCAT + 127) / 128, NTOK / 64);       // 7 x 128
    gemm_tc_kernel<<<g1, 256, 3 * STAGE_BYTES>>>(NCAT, Ee, p_x, p_W, p_bcat, nullptr, p_P);

    tpa_feat_kernel<<<NTOK, 256>>>(qeb, vqc, ent);

    passA_kernel<<<Bb * KVv * NCH, 256>>>();
    passC_kernel<<<Bb * KVv * NCH, 256>>>();

    dim3 g2(Ee / 128, NTOK / 64);                 // 8 x 128
    gemm_tc_kernel<<<g2, 256, 3 * STAGE_BYTES>>>(Ee, Ee, p_a, p_oW, outb, x, out);

    ln_kernel<<<NTOK, 256>>>(out, gamma, beta);
}